// round 1
// baseline (speedup 1.0000x reference)
#include <cuda_runtime.h>
#include <math.h>

#define Bz   8
#define Nseq 4096
#define DIMC 768
#define Hh   12
#define Dh   64
#define BH   (Bz*Hh)        // 96
#define MR   (Bz*Nseq)      // 32768

// ---------------- scratch (device globals; no allocations allowed) ----------
__device__ float g_q[BH*Nseq*Dh];
__device__ float g_k[BH*Nseq*Dh];
__device__ float g_v[BH*Nseq*Dh];
__device__ float g_kcA[BH*2048*Dh];
__device__ float g_kcB[BH*1024*Dh];
__device__ float g_vc[BH*512*Dh];
__device__ float g_kv[BH*Dh*Dh];
__device__ float g_ksum[BH*Dh];
__device__ float g_attn[MR*DIMC];

__device__ __forceinline__ float gelu_f(float t) {
    return 0.5f * t * (1.0f + erff(t * 0.70710678118654752f));
}
__device__ __forceinline__ float fmap_f(float t) {   // elu(t)+1
    return t > 0.0f ? t + 1.0f : expf(t);
}

// ---------------- QKV projection GEMM: X(32768x768) @ {Wq,Wk,Wv} -----------
// grid = (256, 18); blockIdx.y/6 selects weight; epilogue applies fmap for q,k
// and writes head-major (B,H,N,D).
__global__ __launch_bounds__(256) void qkv_gemm(
    const float* __restrict__ X, const float* __restrict__ Wq,
    const float* __restrict__ Wk, const float* __restrict__ Wv)
{
    __shared__ float As[8][128];
    __shared__ float Bs[8][128];
    int nb   = blockIdx.y;
    int wsel = nb / 6;
    const float* W = (wsel == 0) ? Wq : (wsel == 1 ? Wk : Wv);
    float*       O = (wsel == 0) ? g_q : (wsel == 1 ? g_k : g_v);
    int n0 = (nb % 6) * 128;
    int m0 = blockIdx.x * 128;
    int tid = threadIdx.x;
    int a_row = tid >> 1, a_k = (tid & 1) << 2;
    int b_k   = tid >> 5, b_n = (tid & 31) << 2;
    int ty = tid >> 4, tx = tid & 15;

    float acc[8][8];
#pragma unroll
    for (int i = 0; i < 8; i++)
#pragma unroll
        for (int j = 0; j < 8; j++) acc[i][j] = 0.0f;

    const float* Aptr = X + (m0 + a_row) * DIMC + a_k;
    const float* Bptr = W + b_k * DIMC + n0 + b_n;

    for (int k0 = 0; k0 < DIMC; k0 += 8) {
        float4 av = *(const float4*)(Aptr + k0);
        As[a_k + 0][a_row] = av.x;
        As[a_k + 1][a_row] = av.y;
        As[a_k + 2][a_row] = av.z;
        As[a_k + 3][a_row] = av.w;
        *(float4*)&Bs[b_k][b_n] = *(const float4*)(Bptr + k0 * DIMC);
        __syncthreads();
#pragma unroll
        for (int kk = 0; kk < 8; kk++) {
            float af[8], bf[8];
#pragma unroll
            for (int i = 0; i < 8; i++) af[i] = As[kk][ty * 8 + i];
#pragma unroll
            for (int j = 0; j < 8; j++) bf[j] = Bs[kk][tx * 8 + j];
#pragma unroll
            for (int i = 0; i < 8; i++)
#pragma unroll
                for (int j = 0; j < 8; j++)
                    acc[i][j] = fmaf(af[i], bf[j], acc[i][j]);
        }
        __syncthreads();
    }
#pragma unroll
    for (int i = 0; i < 8; i++) {
        int m = m0 + ty * 8 + i;
        int b = m >> 12, n = m & 4095;
#pragma unroll
        for (int j = 0; j < 8; j++) {
            int col = n0 + tx * 8 + j;
            float val = acc[i][j];
            if (wsel < 2) val = fmap_f(val);
            int h = col >> 6, d = col & 63;
            O[((b * Hh + h) * Nseq + n) * Dh + d] = val;
        }
    }
}

// ---------------- final GEMM: g_attn(32768x768) @ Wo + bo -> out ------------
__global__ __launch_bounds__(256) void out_gemm(
    const float* __restrict__ W, const float* __restrict__ bias,
    float* __restrict__ out)
{
    __shared__ float As[8][128];
    __shared__ float Bs[8][128];
    int n0 = blockIdx.y * 128;
    int m0 = blockIdx.x * 128;
    int tid = threadIdx.x;
    int a_row = tid >> 1, a_k = (tid & 1) << 2;
    int b_k   = tid >> 5, b_n = (tid & 31) << 2;
    int ty = tid >> 4, tx = tid & 15;

    float acc[8][8];
#pragma unroll
    for (int i = 0; i < 8; i++)
#pragma unroll
        for (int j = 0; j < 8; j++) acc[i][j] = 0.0f;

    const float* Aptr = g_attn + (m0 + a_row) * DIMC + a_k;
    const float* Bptr = W + b_k * DIMC + n0 + b_n;

    for (int k0 = 0; k0 < DIMC; k0 += 8) {
        float4 av = *(const float4*)(Aptr + k0);
        As[a_k + 0][a_row] = av.x;
        As[a_k + 1][a_row] = av.y;
        As[a_k + 2][a_row] = av.z;
        As[a_k + 3][a_row] = av.w;
        *(float4*)&Bs[b_k][b_n] = *(const float4*)(Bptr + k0 * DIMC);
        __syncthreads();
#pragma unroll
        for (int kk = 0; kk < 8; kk++) {
            float af[8], bf[8];
#pragma unroll
            for (int i = 0; i < 8; i++) af[i] = As[kk][ty * 8 + i];
#pragma unroll
            for (int j = 0; j < 8; j++) bf[j] = Bs[kk][tx * 8 + j];
#pragma unroll
            for (int i = 0; i < 8; i++)
#pragma unroll
                for (int j = 0; j < 8; j++)
                    acc[i][j] = fmaf(af[i], bf[j], acc[i][j]);
        }
        __syncthreads();
    }
#pragma unroll
    for (int i = 0; i < 8; i++) {
        int m = m0 + ty * 8 + i;
#pragma unroll
        for (int j = 0; j < 8; j++) {
            int col = n0 + tx * 8 + j;
            out[m * DIMC + col] = acc[i][j] + bias[col];
        }
    }
}

// ---------------- vc pooling: mean over 8 consecutive tokens ----------------
__global__ void vpool_kernel()
{
    int idx = blockIdx.x * 256 + threadIdx.x;
    if (idx >= BH * 512 * Dh) return;
    int d   = idx & 63;
    int rest = idx >> 6;
    int n   = rest & 511;
    int bh  = rest >> 9;
    const float* src = g_v + (bh * 4096 + n * 8) * 64 + d;
    float s = 0.0f;
#pragma unroll
    for (int j = 0; j < 8; j++) s += src[j * 64];
    g_vc[idx] = s * 0.125f;
}

// ---------------- kc pooling stage: pool pairs then MLP(LN+gelu) ------------
// 256 threads = 64 rows, 4 lanes per row, 16 columns each.
__global__ __launch_bounds__(256) void pool_mlp(
    int stage,
    const float* __restrict__ pW, const float* __restrict__ pb,
    const float* __restrict__ pg, const float* __restrict__ pbe)
{
    __shared__ float Ws[64][64];
    __shared__ float rows[64][65];
    __shared__ float bs[64], gs[64], bes[64];

    const float* in; float* out; int s_in, s_out;
    if (stage == 0)      { in = g_k;   out = g_kcA; s_in = 4096; s_out = 2048; }
    else if (stage == 1) { in = g_kcA; out = g_kcB; s_in = 2048; s_out = 1024; }
    else                 { in = g_kcB; out = g_kcA; s_in = 1024; s_out = 512;  }
    pW += stage * 4096; pb += stage * 64; pg += stage * 64; pbe += stage * 64;

    int tid = threadIdx.x;
    for (int i = tid; i < 4096; i += 256) Ws[i >> 6][i & 63] = pW[i];
    if (tid < 64) { bs[tid] = pb[tid]; gs[tid] = pg[tid]; bes[tid] = pbe[tid]; }

    int r = tid >> 2, lane4 = tid & 3, c0 = lane4 * 16;
    int rg = blockIdx.x * 64 + r;
    int bh = rg / s_out, n = rg - bh * s_out;
    const float* src = in + (bh * s_in + 2 * n) * 64;
    for (int e = lane4; e < 64; e += 4)
        rows[r][e] = 0.5f * (src[e] + src[64 + e]);
    __syncthreads();

    float y[16];
#pragma unroll
    for (int j = 0; j < 16; j++) y[j] = bs[c0 + j];
    for (int e = 0; e < 64; e++) {
        float xv = rows[r][e];
#pragma unroll
        for (int j = 0; j < 16; j++) y[j] = fmaf(xv, Ws[e][c0 + j], y[j]);
    }
    float s1 = 0.0f, s2 = 0.0f;
#pragma unroll
    for (int j = 0; j < 16; j++) { s1 += y[j]; s2 += y[j] * y[j]; }
    s1 += __shfl_xor_sync(~0u, s1, 1); s2 += __shfl_xor_sync(~0u, s2, 1);
    s1 += __shfl_xor_sync(~0u, s1, 2); s2 += __shfl_xor_sync(~0u, s2, 2);
    float mu  = s1 * (1.0f / 64.0f);
    float var = s2 * (1.0f / 64.0f) - mu * mu;
    float inv = rsqrtf(var + 1e-5f);

    float* orow = out + rg * 64;
#pragma unroll
    for (int j = 0; j < 16; j++) {
        float t = (y[j] - mu) * inv * gs[c0 + j] + bes[c0 + j];
        orow[c0 + j] = gelu_f(t);
    }
}

// ---------------- kv = (kc/sqrt(512))^T vc, plus k_sum, per (b,h) -----------
__global__ __launch_bounds__(256) void kv_kernel()
{
    int bh = blockIdx.x;
    __shared__ float ks[64][65];
    __shared__ float vs[64][65];
    int tid = threadIdx.x;
    int td = tid & 15, te = tid >> 4;
    float acc[4][4];
#pragma unroll
    for (int i = 0; i < 4; i++)
#pragma unroll
        for (int j = 0; j < 4; j++) acc[i][j] = 0.0f;
    float colsum = 0.0f;
    const float scale = rsqrtf(512.0f);

    for (int nt = 0; nt < 512; nt += 64) {
        for (int i = tid; i < 4096; i += 256) {
            int rr = i >> 6, cc = i & 63;
            ks[rr][cc] = g_kcA[(bh * 512 + nt + rr) * 64 + cc] * scale;
            vs[rr][cc] = g_vc [(bh * 512 + nt + rr) * 64 + cc];
        }
        __syncthreads();
        if (tid < 64) {
            for (int rr = 0; rr < 64; rr++) colsum += ks[rr][tid];
        }
#pragma unroll 4
        for (int nn = 0; nn < 64; nn++) {
            float a[4], bb[4];
#pragma unroll
            for (int i = 0; i < 4; i++) a[i]  = ks[nn][td * 4 + i];
#pragma unroll
            for (int j = 0; j < 4; j++) bb[j] = vs[nn][te * 4 + j];
#pragma unroll
            for (int i = 0; i < 4; i++)
#pragma unroll
                for (int j = 0; j < 4; j++)
                    acc[i][j] = fmaf(a[i], bb[j], acc[i][j]);
        }
        __syncthreads();
    }
#pragma unroll
    for (int i = 0; i < 4; i++)
#pragma unroll
        for (int j = 0; j < 4; j++)
            g_kv[(bh * 64 + td * 4 + i) * 64 + te * 4 + j] = acc[i][j];
    if (tid < 64) g_ksum[bh * 64 + tid] = colsum;
}

// ---------------- fused: out=q@kv, /(q.k_sum+1e-6), 3x exp MLP, re-layout ---
// grid = 96*64 blocks; 64 rows per block; 4 lanes/row.
__global__ __launch_bounds__(256) void attn_mlp(
    const float* __restrict__ eW, const float* __restrict__ eb,
    const float* __restrict__ eg, const float* __restrict__ ebe)
{
    __shared__ float bufA[64][64];   // kv, then reused per-stage for exp_W
    __shared__ float rows[64][65];
    __shared__ float ksm[64];
    __shared__ float vb[64], vg[64], vbe[64];

    int bh = blockIdx.x >> 6;
    int n0 = (blockIdx.x & 63) << 6;
    int tid = threadIdx.x;
    int r = tid >> 2, lane4 = tid & 3, c0 = lane4 * 16;

    for (int i = tid; i < 4096; i += 256) bufA[i >> 6][i & 63] = g_kv[bh * 4096 + i];
    if (tid < 64) ksm[tid] = g_ksum[bh * 64 + tid];
    const float* qrow = g_q + (bh * 4096 + n0 + r) * 64;
    for (int e = lane4; e < 64; e += 4) rows[r][e] = qrow[e];
    __syncthreads();

    float y[16];
#pragma unroll
    for (int j = 0; j < 16; j++) y[j] = 0.0f;
    for (int e = 0; e < 64; e++) {
        float qe = rows[r][e];
#pragma unroll
        for (int j = 0; j < 16; j++) y[j] = fmaf(qe, bufA[e][c0 + j], y[j]);
    }
    float dp = 0.0f;
    for (int e = lane4; e < 64; e += 4) dp += rows[r][e] * ksm[e];
    dp += __shfl_xor_sync(~0u, dp, 1);
    dp += __shfl_xor_sync(~0u, dp, 2);
    float inv = 1.0f / (dp + 1e-6f);
    __syncwarp();
#pragma unroll
    for (int j = 0; j < 16; j++) rows[r][c0 + j] = y[j] * inv;

    for (int s = 2; s >= 0; s--) {
        __syncthreads();
        for (int i = tid; i < 4096; i += 256) bufA[i >> 6][i & 63] = eW[s * 4096 + i];
        if (tid < 64) { vb[tid] = eb[s * 64 + tid]; vg[tid] = eg[s * 64 + tid]; vbe[tid] = ebe[s * 64 + tid]; }
        __syncthreads();

        float z[16];
#pragma unroll
        for (int j = 0; j < 16; j++) z[j] = vb[c0 + j];
        for (int e = 0; e < 64; e++) {
            float xv = rows[r][e];
#pragma unroll
            for (int j = 0; j < 16; j++) z[j] = fmaf(xv, bufA[e][c0 + j], z[j]);
        }
        float s1 = 0.0f, s2 = 0.0f;
#pragma unroll
        for (int j = 0; j < 16; j++) { s1 += z[j]; s2 += z[j] * z[j]; }
        s1 += __shfl_xor_sync(~0u, s1, 1); s2 += __shfl_xor_sync(~0u, s2, 1);
        s1 += __shfl_xor_sync(~0u, s1, 2); s2 += __shfl_xor_sync(~0u, s2, 2);
        float mu   = s1 * (1.0f / 64.0f);
        float var  = s2 * (1.0f / 64.0f) - mu * mu;
        float rinv = rsqrtf(var + 1e-5f);
        __syncwarp();
#pragma unroll
        for (int j = 0; j < 16; j++)
            rows[r][c0 + j] = gelu_f((z[j] - mu) * rinv * vg[c0 + j] + vbe[c0 + j]);
    }
    __syncwarp();
    int b = bh / Hh, h = bh % Hh;
    float* orow = g_attn + (b * 4096 + n0 + r) * DIMC + h * 64;
#pragma unroll
    for (int j = 0; j < 16; j++) orow[c0 + j] = rows[r][c0 + j];
}

// ---------------- launch --------------------------------------------------
extern "C" void kernel_launch(void* const* d_in, const int* in_sizes, int n_in,
                              void* d_out, int out_size)
{
    const float* x   = (const float*)d_in[0];
    const float* Wq  = (const float*)d_in[1];
    const float* Wk  = (const float*)d_in[2];
    const float* Wv  = (const float*)d_in[3];
    const float* pW  = (const float*)d_in[4];
    const float* pb  = (const float*)d_in[5];
    const float* pg  = (const float*)d_in[6];
    const float* pbe = (const float*)d_in[7];
    const float* eW  = (const float*)d_in[8];
    const float* eb  = (const float*)d_in[9];
    const float* eg  = (const float*)d_in[10];
    const float* ebe = (const float*)d_in[11];
    const float* Wo  = (const float*)d_in[12];
    const float* bo  = (const float*)d_in[13];
    float* out = (float*)d_out;

    qkv_gemm<<<dim3(MR / 128, 18), 256>>>(x, Wq, Wk, Wv);
    vpool_kernel<<<(BH * 512 * Dh + 255) / 256, 256>>>();
    pool_mlp<<<BH * 2048 / 64, 256>>>(0, pW, pb, pg, pbe);
    pool_mlp<<<BH * 1024 / 64, 256>>>(1, pW, pb, pg, pbe);
    pool_mlp<<<BH * 512 / 64, 256>>>(2, pW, pb, pg, pbe);
    kv_kernel<<<BH, 256>>>();
    attn_mlp<<<BH * 64, 256>>>(eW, eb, eg, ebe);
    out_gemm<<<dim3(MR / 128, 6), 256>>>(Wo, bo, out);
}

// round 2
// speedup vs baseline: 1.5451x; 1.5451x over previous
#include <cuda_runtime.h>
#include <math.h>
#include <stdint.h>

#define Bz   8
#define Nseq 4096
#define DIMC 768
#define Hh   12
#define Dh   64
#define BH   (Bz*Hh)        // 96
#define MR   (Bz*Nseq)      // 32768

// ---------------- scratch (device globals; no allocations allowed) ----------
__device__ float g_q[BH*Nseq*Dh];
__device__ float g_k[BH*Nseq*Dh];
__device__ float g_v[BH*Nseq*Dh];
__device__ float g_kcA[BH*2048*Dh];
__device__ float g_kcB[BH*1024*Dh];
__device__ float g_vc[BH*512*Dh];
__device__ float g_kv[BH*Dh*Dh];
__device__ float g_ksum[BH*Dh];
__device__ float g_attn[MR*DIMC];

__device__ __forceinline__ float gelu_f(float t) {
    return 0.5f * t * (1.0f + erff(t * 0.70710678118654752f));
}
__device__ __forceinline__ float fmap_f(float t) {   // elu(t)+1
    return t > 0.0f ? t + 1.0f : expf(t);
}
__device__ __forceinline__ uint32_t f2tf32(float f) {
    uint32_t r;
    asm("cvt.rna.tf32.f32 %0, %1;" : "=r"(r) : "f"(f));
    return r;
}
__device__ __forceinline__ void mma_tf32(float c[4],
    uint32_t a0, uint32_t a1, uint32_t a2, uint32_t a3,
    uint32_t b0, uint32_t b1)
{
    asm volatile(
        "mma.sync.aligned.m16n8k8.row.col.f32.tf32.tf32.f32 "
        "{%0,%1,%2,%3}, {%4,%5,%6,%7}, {%8,%9}, {%0,%1,%2,%3};"
        : "+f"(c[0]), "+f"(c[1]), "+f"(c[2]), "+f"(c[3])
        : "r"(a0), "r"(a1), "r"(a2), "r"(a3), "r"(b0), "r"(b1));
}

// =======================================================================
// Tensor-core tf32 GEMM body: C[128x128] tile of  A(Mx768) @ W(768x768)
// 8 warps as 4(M) x 2(N); warp tile 32x64; BK=32.
// Shared: As[m][k] stride 36, Bs[k][n] stride 136 (conflict-free frags).
// =======================================================================
#define GEMM_SMEM_DECL \
    __shared__ uint32_t As[128][36]; \
    __shared__ uint32_t Bs[32][136];

#define GEMM_BODY(APTR_EXPR) \
    int tid = threadIdx.x; \
    int warp = tid >> 5, lane = tid & 31; \
    int g = lane >> 2, t = lane & 3; \
    int wm = warp >> 1, wn = warp & 1; \
    int a_row = tid >> 1, a_col = (tid & 1) << 4; \
    int b_row = tid >> 3, b_col = (tid & 7) << 4; \
    float acc[2][8][4]; \
    _Pragma("unroll") \
    for (int i = 0; i < 2; i++) \
        _Pragma("unroll") \
        for (int j = 0; j < 8; j++) \
            _Pragma("unroll") \
            for (int q = 0; q < 4; q++) acc[i][j][q] = 0.0f; \
    for (int k0 = 0; k0 < DIMC; k0 += 32) { \
        const float* ap = (APTR_EXPR) + k0 + a_col; \
        const float* bp = W + (size_t)(k0 + b_row) * DIMC + n0 + b_col; \
        _Pragma("unroll") \
        for (int u = 0; u < 16; u += 4) { \
            float4 av = *(const float4*)(ap + u); \
            As[a_row][a_col + u + 0] = f2tf32(av.x); \
            As[a_row][a_col + u + 1] = f2tf32(av.y); \
            As[a_row][a_col + u + 2] = f2tf32(av.z); \
            As[a_row][a_col + u + 3] = f2tf32(av.w); \
            float4 bv = *(const float4*)(bp + u); \
            Bs[b_row][b_col + u + 0] = f2tf32(bv.x); \
            Bs[b_row][b_col + u + 1] = f2tf32(bv.y); \
            Bs[b_row][b_col + u + 2] = f2tf32(bv.z); \
            Bs[b_row][b_col + u + 3] = f2tf32(bv.w); \
        } \
        __syncthreads(); \
        _Pragma("unroll") \
        for (int kk = 0; kk < 4; kk++) { \
            int ks = kk * 8; \
            uint32_t af[2][4]; \
            _Pragma("unroll") \
            for (int i = 0; i < 2; i++) { \
                int rb = wm * 32 + i * 16; \
                af[i][0] = As[rb + g    ][ks + t    ]; \
                af[i][1] = As[rb + g + 8][ks + t    ]; \
                af[i][2] = As[rb + g    ][ks + t + 4]; \
                af[i][3] = As[rb + g + 8][ks + t + 4]; \
            } \
            uint32_t bf[8][2]; \
            _Pragma("unroll") \
            for (int j = 0; j < 8; j++) { \
                int cb = wn * 64 + j * 8 + g; \
                bf[j][0] = Bs[ks + t    ][cb]; \
                bf[j][1] = Bs[ks + t + 4][cb]; \
            } \
            _Pragma("unroll") \
            for (int i = 0; i < 2; i++) \
                _Pragma("unroll") \
                for (int j = 0; j < 8; j++) \
                    mma_tf32(acc[i][j], af[i][0], af[i][1], af[i][2], af[i][3], \
                             bf[j][0], bf[j][1]); \
        } \
        __syncthreads(); \
    }

// ---------------- QKV projection GEMM -----------------
// grid = (256, 18); blockIdx.y/6 selects weight; epilogue applies fmap for q,k
// and writes head-major (B,H,N,D).
__global__ __launch_bounds__(256) void qkv_gemm(
    const float* __restrict__ X, const float* __restrict__ Wq,
    const float* __restrict__ Wk, const float* __restrict__ Wv)
{
    GEMM_SMEM_DECL
    int nb   = blockIdx.y;
    int wsel = nb / 6;
    const float* W = (wsel == 0) ? Wq : (wsel == 1 ? Wk : Wv);
    float*       O = (wsel == 0) ? g_q : (wsel == 1 ? g_k : g_v);
    int n0 = (nb % 6) * 128;
    int m0 = blockIdx.x * 128;

    GEMM_BODY(X + (size_t)(m0 + a_row) * DIMC)

#pragma unroll
    for (int i = 0; i < 2; i++) {
#pragma unroll
        for (int j = 0; j < 8; j++) {
            int r0 = m0 + wm * 32 + i * 16 + g;
            int c  = n0 + wn * 64 + j * 8 + t * 2;
            int h = c >> 6, d = c & 63;
#pragma unroll
            for (int half = 0; half < 2; half++) {
                int m = half ? r0 + 8 : r0;
                int b = m >> 12, n = m & 4095;
                float v0 = acc[i][j][half * 2 + 0];
                float v1 = acc[i][j][half * 2 + 1];
                if (wsel < 2) { v0 = fmap_f(v0); v1 = fmap_f(v1); }
                float* dst = O + (((size_t)(b * Hh + h) * Nseq + n) * Dh + d);
                dst[0] = v0; dst[1] = v1;
            }
        }
    }
}

// ---------------- final GEMM: g_attn(32768x768) @ Wo + bo -> out ------------
__global__ __launch_bounds__(256) void out_gemm(
    const float* __restrict__ W, const float* __restrict__ bias,
    float* __restrict__ out)
{
    GEMM_SMEM_DECL
    int n0 = blockIdx.y * 128;
    int m0 = blockIdx.x * 128;

    GEMM_BODY(g_attn + (size_t)(m0 + a_row) * DIMC)

#pragma unroll
    for (int i = 0; i < 2; i++) {
#pragma unroll
        for (int j = 0; j < 8; j++) {
            int r0 = m0 + wm * 32 + i * 16 + g;
            int c  = n0 + wn * 64 + j * 8 + t * 2;
            float b0 = bias[c], b1 = bias[c + 1];
            out[(size_t)r0 * DIMC + c]           = acc[i][j][0] + b0;
            out[(size_t)r0 * DIMC + c + 1]       = acc[i][j][1] + b1;
            out[(size_t)(r0 + 8) * DIMC + c]     = acc[i][j][2] + b0;
            out[(size_t)(r0 + 8) * DIMC + c + 1] = acc[i][j][3] + b1;
        }
    }
}

// ---------------- vc pooling: mean over 8 consecutive tokens ----------------
__global__ void vpool_kernel()
{
    int idx = blockIdx.x * 256 + threadIdx.x;
    if (idx >= BH * 512 * Dh) return;
    int d   = idx & 63;
    int rest = idx >> 6;
    int n   = rest & 511;
    int bh  = rest >> 9;
    const float* src = g_v + (bh * 4096 + n * 8) * 64 + d;
    float s = 0.0f;
#pragma unroll
    for (int j = 0; j < 8; j++) s += src[j * 64];
    g_vc[idx] = s * 0.125f;
}

// ---------------- kc pooling stage: pool pairs then MLP(LN+gelu) ------------
__global__ __launch_bounds__(256) void pool_mlp(
    int stage,
    const float* __restrict__ pW, const float* __restrict__ pb,
    const float* __restrict__ pg, const float* __restrict__ pbe)
{
    __shared__ float Ws[64][64];
    __shared__ float rows[64][65];
    __shared__ float bs[64], gs[64], bes[64];

    const float* in; float* out; int s_in, s_out;
    if (stage == 0)      { in = g_k;   out = g_kcA; s_in = 4096; s_out = 2048; }
    else if (stage == 1) { in = g_kcA; out = g_kcB; s_in = 2048; s_out = 1024; }
    else                 { in = g_kcB; out = g_kcA; s_in = 1024; s_out = 512;  }
    pW += stage * 4096; pb += stage * 64; pg += stage * 64; pbe += stage * 64;

    int tid = threadIdx.x;
    for (int i = tid; i < 4096; i += 256) Ws[i >> 6][i & 63] = pW[i];
    if (tid < 64) { bs[tid] = pb[tid]; gs[tid] = pg[tid]; bes[tid] = pbe[tid]; }

    int r = tid >> 2, lane4 = tid & 3, c0 = lane4 * 16;
    int rg = blockIdx.x * 64 + r;
    int bh = rg / s_out, n = rg - bh * s_out;
    const float* src = in + (bh * s_in + 2 * n) * 64;
    for (int e = lane4; e < 64; e += 4)
        rows[r][e] = 0.5f * (src[e] + src[64 + e]);
    __syncthreads();

    float y[16];
#pragma unroll
    for (int j = 0; j < 16; j++) y[j] = bs[c0 + j];
    for (int e = 0; e < 64; e++) {
        float xv = rows[r][e];
#pragma unroll
        for (int j = 0; j < 16; j++) y[j] = fmaf(xv, Ws[e][c0 + j], y[j]);
    }
    float s1 = 0.0f, s2 = 0.0f;
#pragma unroll
    for (int j = 0; j < 16; j++) { s1 += y[j]; s2 += y[j] * y[j]; }
    s1 += __shfl_xor_sync(~0u, s1, 1); s2 += __shfl_xor_sync(~0u, s2, 1);
    s1 += __shfl_xor_sync(~0u, s1, 2); s2 += __shfl_xor_sync(~0u, s2, 2);
    float mu  = s1 * (1.0f / 64.0f);
    float var = s2 * (1.0f / 64.0f) - mu * mu;
    float inv = rsqrtf(var + 1e-5f);

    float* orow = out + rg * 64;
#pragma unroll
    for (int j = 0; j < 16; j++) {
        float t = (y[j] - mu) * inv * gs[c0 + j] + bes[c0 + j];
        orow[c0 + j] = gelu_f(t);
    }
}

// ---------------- kv = (kc/sqrt(512))^T vc, plus k_sum, per (b,h) -----------
__global__ __launch_bounds__(256) void kv_kernel()
{
    int bh = blockIdx.x;
    __shared__ float ks[64][65];
    __shared__ float vs[64][65];
    int tid = threadIdx.x;
    int td = tid & 15, te = tid >> 4;
    float acc[4][4];
#pragma unroll
    for (int i = 0; i < 4; i++)
#pragma unroll
        for (int j = 0; j < 4; j++) acc[i][j] = 0.0f;
    float colsum = 0.0f;
    const float scale = rsqrtf(512.0f);

    for (int nt = 0; nt < 512; nt += 64) {
        for (int i = tid; i < 4096; i += 256) {
            int rr = i >> 6, cc = i & 63;
            ks[rr][cc] = g_kcA[(bh * 512 + nt + rr) * 64 + cc] * scale;
            vs[rr][cc] = g_vc [(bh * 512 + nt + rr) * 64 + cc];
        }
        __syncthreads();
        if (tid < 64) {
            for (int rr = 0; rr < 64; rr++) colsum += ks[rr][tid];
        }
#pragma unroll 4
        for (int nn = 0; nn < 64; nn++) {
            float a[4], bb[4];
#pragma unroll
            for (int i = 0; i < 4; i++) a[i]  = ks[nn][td * 4 + i];
#pragma unroll
            for (int j = 0; j < 4; j++) bb[j] = vs[nn][te * 4 + j];
#pragma unroll
            for (int i = 0; i < 4; i++)
#pragma unroll
                for (int j = 0; j < 4; j++)
                    acc[i][j] = fmaf(a[i], bb[j], acc[i][j]);
        }
        __syncthreads();
    }
#pragma unroll
    for (int i = 0; i < 4; i++)
#pragma unroll
        for (int j = 0; j < 4; j++)
            g_kv[(bh * 64 + td * 4 + i) * 64 + te * 4 + j] = acc[i][j];
    if (tid < 64) g_ksum[bh * 64 + tid] = colsum;
}

// ---------------- fused: out=q@kv, /(q.k_sum+1e-6), 3x exp MLP, re-layout ---
__global__ __launch_bounds__(256) void attn_mlp(
    const float* __restrict__ eW, const float* __restrict__ eb,
    const float* __restrict__ eg, const float* __restrict__ ebe)
{
    __shared__ float bufA[64][64];
    __shared__ float rows[64][65];
    __shared__ float ksm[64];
    __shared__ float vb[64], vg[64], vbe[64];

    int bh = blockIdx.x >> 6;
    int n0 = (blockIdx.x & 63) << 6;
    int tid = threadIdx.x;
    int r = tid >> 2, lane4 = tid & 3, c0 = lane4 * 16;

    for (int i = tid; i < 4096; i += 256) bufA[i >> 6][i & 63] = g_kv[bh * 4096 + i];
    if (tid < 64) ksm[tid] = g_ksum[bh * 64 + tid];
    const float* qrow = g_q + (bh * 4096 + n0 + r) * 64;
    for (int e = lane4; e < 64; e += 4) rows[r][e] = qrow[e];
    __syncthreads();

    float y[16];
#pragma unroll
    for (int j = 0; j < 16; j++) y[j] = 0.0f;
    for (int e = 0; e < 64; e++) {
        float qe = rows[r][e];
#pragma unroll
        for (int j = 0; j < 16; j++) y[j] = fmaf(qe, bufA[e][c0 + j], y[j]);
    }
    float dp = 0.0f;
    for (int e = lane4; e < 64; e += 4) dp += rows[r][e] * ksm[e];
    dp += __shfl_xor_sync(~0u, dp, 1);
    dp += __shfl_xor_sync(~0u, dp, 2);
    float inv = 1.0f / (dp + 1e-6f);
    __syncwarp();
#pragma unroll
    for (int j = 0; j < 16; j++) rows[r][c0 + j] = y[j] * inv;

    for (int s = 2; s >= 0; s--) {
        __syncthreads();
        for (int i = tid; i < 4096; i += 256) bufA[i >> 6][i & 63] = eW[s * 4096 + i];
        if (tid < 64) { vb[tid] = eb[s * 64 + tid]; vg[tid] = eg[s * 64 + tid]; vbe[tid] = ebe[s * 64 + tid]; }
        __syncthreads();

        float z[16];
#pragma unroll
        for (int j = 0; j < 16; j++) z[j] = vb[c0 + j];
        for (int e = 0; e < 64; e++) {
            float xv = rows[r][e];
#pragma unroll
            for (int j = 0; j < 16; j++) z[j] = fmaf(xv, bufA[e][c0 + j], z[j]);
        }
        float s1 = 0.0f, s2 = 0.0f;
#pragma unroll
        for (int j = 0; j < 16; j++) { s1 += z[j]; s2 += z[j] * z[j]; }
        s1 += __shfl_xor_sync(~0u, s1, 1); s2 += __shfl_xor_sync(~0u, s2, 1);
        s1 += __shfl_xor_sync(~0u, s1, 2); s2 += __shfl_xor_sync(~0u, s2, 2);
        float mu   = s1 * (1.0f / 64.0f);
        float var  = s2 * (1.0f / 64.0f) - mu * mu;
        float rinv = rsqrtf(var + 1e-5f);
        __syncwarp();
#pragma unroll
        for (int j = 0; j < 16; j++)
            rows[r][c0 + j] = gelu_f((z[j] - mu) * rinv * vg[c0 + j] + vbe[c0 + j]);
    }
    __syncwarp();
    int b = bh / Hh, h = bh % Hh;
    float* orow = g_attn + (b * 4096 + n0 + r) * DIMC + h * 64;
#pragma unroll
    for (int j = 0; j < 16; j++) orow[c0 + j] = rows[r][c0 + j];
}

// ---------------- launch --------------------------------------------------
extern "C" void kernel_launch(void* const* d_in, const int* in_sizes, int n_in,
                              void* d_out, int out_size)
{
    const float* x   = (const float*)d_in[0];
    const float* Wq  = (const float*)d_in[1];
    const float* Wk  = (const float*)d_in[2];
    const float* Wv  = (const float*)d_in[3];
    const float* pW  = (const float*)d_in[4];
    const float* pb  = (const float*)d_in[5];
    const float* pg  = (const float*)d_in[6];
    const float* pbe = (const float*)d_in[7];
    const float* eW  = (const float*)d_in[8];
    const float* eb  = (const float*)d_in[9];
    const float* eg  = (const float*)d_in[10];
    const float* ebe = (const float*)d_in[11];
    const float* Wo  = (const float*)d_in[12];
    const float* bo  = (const float*)d_in[13];
    float* out = (float*)d_out;

    qkv_gemm<<<dim3(MR / 128, 18), 256>>>(x, Wq, Wk, Wv);
    vpool_kernel<<<(BH * 512 * Dh + 255) / 256, 256>>>();
    pool_mlp<<<BH * 2048 / 64, 256>>>(0, pW, pb, pg, pbe);
    pool_mlp<<<BH * 1024 / 64, 256>>>(1, pW, pb, pg, pbe);
    pool_mlp<<<BH * 512 / 64, 256>>>(2, pW, pb, pg, pbe);
    kv_kernel<<<BH, 256>>>();
    attn_mlp<<<BH * 64, 256>>>(eW, eb, eg, ebe);
    out_gemm<<<dim3(MR / 128, 6), 256>>>(Wo, bo, out);
}

// round 3
// speedup vs baseline: 1.6394x; 1.0611x over previous
#include <cuda_runtime.h>
#include <math.h>
#include <stdint.h>

#define Bz   8
#define Nseq 4096
#define DIMC 768
#define Hh   12
#define Dh   64
#define BH   (Bz*Hh)        // 96
#define MR   (Bz*Nseq)      // 32768

// ---------------- scratch (device globals; no allocations allowed) ----------
__device__ float g_q[BH*Nseq*Dh];
__device__ float g_k[BH*Nseq*Dh];
__device__ float g_v[BH*Nseq*Dh];
__device__ float g_kcA[BH*2048*Dh];
__device__ float g_kcB[BH*1024*Dh];
__device__ float g_vc[BH*512*Dh];
__device__ float g_kv[BH*Dh*Dh];
__device__ float g_ksum[BH*Dh];
__device__ float g_attn[MR*DIMC];

__device__ __forceinline__ float gelu_f(float t) {
    return 0.5f * t * (1.0f + erff(t * 0.70710678118654752f));
}
__device__ __forceinline__ float fmap_f(float t) {   // elu(t)+1
    return t > 0.0f ? t + 1.0f : expf(t);
}
__device__ __forceinline__ uint32_t f2tf32(float f) {
    uint32_t r;
    asm("cvt.rna.tf32.f32 %0, %1;" : "=r"(r) : "f"(f));
    return r;
}
__device__ __forceinline__ void mma_tf32(float c[4],
    uint32_t a0, uint32_t a1, uint32_t a2, uint32_t a3,
    uint32_t b0, uint32_t b1)
{
    asm volatile(
        "mma.sync.aligned.m16n8k8.row.col.f32.tf32.tf32.f32 "
        "{%0,%1,%2,%3}, {%4,%5,%6,%7}, {%8,%9}, {%0,%1,%2,%3};"
        : "+f"(c[0]), "+f"(c[1]), "+f"(c[2]), "+f"(c[3])
        : "r"(a0), "r"(a1), "r"(a2), "r"(a3), "r"(b0), "r"(b1));
}

// =======================================================================
// Tensor-core tf32 GEMM body, double-buffered & register-staged.
// C[128x128] tile of A(Mx768) @ W(768x768); 8 warps = 4(M) x 2(N);
// warp tile 32x64; BK=32.
// Dynamic smem: As[2][128][36] + Bs[2][32][136] (uint32 tf32 bits).
// =======================================================================
#define AS_STRIDE 36
#define BS_STRIDE 136
#define AS_TILE   (128 * AS_STRIDE)
#define BS_TILE   (32 * BS_STRIDE)
#define GEMM_SMEM_BYTES ((2 * AS_TILE + 2 * BS_TILE) * 4)

#define GEMM_PROLOG \
    extern __shared__ uint32_t smemg[]; \
    uint32_t* Asb = smemg; \
    uint32_t* Bsb = smemg + 2 * AS_TILE; \
    int tid = threadIdx.x; \
    int warp = tid >> 5, lane = tid & 31; \
    int g = lane >> 2, t = lane & 3; \
    int wm = warp >> 1, wn = warp & 1; \
    int a_row = tid >> 1, a_col = (tid & 1) << 4; \
    int b_row = tid >> 3, b_col = (tid & 7) << 4; \
    float acc[2][8][4]; \
    _Pragma("unroll") \
    for (int i = 0; i < 2; i++) \
        _Pragma("unroll") \
        for (int j = 0; j < 8; j++) \
            _Pragma("unroll") \
            for (int q = 0; q < 4; q++) acc[i][j][q] = 0.0f; \
    float4 areg[4], breg[4];

#define GEMM_LOAD(APTR_BASE, K0) { \
    const float* ap_ = (APTR_BASE) + (K0) + a_col; \
    const float* bp_ = W + (size_t)((K0) + b_row) * DIMC + n0 + b_col; \
    _Pragma("unroll") \
    for (int u = 0; u < 4; u++) { \
        areg[u] = *(const float4*)(ap_ + u * 4); \
        breg[u] = *(const float4*)(bp_ + u * 4); \
    } }

#define GEMM_STORE(BUF) { \
    uint32_t* asd = Asb + (BUF) * AS_TILE + a_row * AS_STRIDE + a_col; \
    uint32_t* bsd = Bsb + (BUF) * BS_TILE + b_row * BS_STRIDE + b_col; \
    _Pragma("unroll") \
    for (int u = 0; u < 4; u++) { \
        asd[u * 4 + 0] = f2tf32(areg[u].x); \
        asd[u * 4 + 1] = f2tf32(areg[u].y); \
        asd[u * 4 + 2] = f2tf32(areg[u].z); \
        asd[u * 4 + 3] = f2tf32(areg[u].w); \
        bsd[u * 4 + 0] = f2tf32(breg[u].x); \
        bsd[u * 4 + 1] = f2tf32(breg[u].y); \
        bsd[u * 4 + 2] = f2tf32(breg[u].z); \
        bsd[u * 4 + 3] = f2tf32(breg[u].w); \
    } }

#define GEMM_COMPUTE(BUF) { \
    const uint32_t* Asc = Asb + (BUF) * AS_TILE; \
    const uint32_t* Bsc = Bsb + (BUF) * BS_TILE; \
    _Pragma("unroll") \
    for (int kk = 0; kk < 4; kk++) { \
        int ks = kk * 8; \
        uint32_t af[2][4]; \
        _Pragma("unroll") \
        for (int i = 0; i < 2; i++) { \
            int rb = wm * 32 + i * 16; \
            af[i][0] = Asc[(rb + g    ) * AS_STRIDE + ks + t    ]; \
            af[i][1] = Asc[(rb + g + 8) * AS_STRIDE + ks + t    ]; \
            af[i][2] = Asc[(rb + g    ) * AS_STRIDE + ks + t + 4]; \
            af[i][3] = Asc[(rb + g + 8) * AS_STRIDE + ks + t + 4]; \
        } \
        uint32_t bf[8][2]; \
        _Pragma("unroll") \
        for (int j = 0; j < 8; j++) { \
            int cb = wn * 64 + j * 8 + g; \
            bf[j][0] = Bsc[(ks + t    ) * BS_STRIDE + cb]; \
            bf[j][1] = Bsc[(ks + t + 4) * BS_STRIDE + cb]; \
        } \
        _Pragma("unroll") \
        for (int i = 0; i < 2; i++) \
            _Pragma("unroll") \
            for (int j = 0; j < 8; j++) \
                mma_tf32(acc[i][j], af[i][0], af[i][1], af[i][2], af[i][3], \
                         bf[j][0], bf[j][1]); \
    } }

#define GEMM_MAINLOOP(APTR_BASE) \
    GEMM_LOAD(APTR_BASE, 0) \
    GEMM_STORE(0) \
    __syncthreads(); \
    _Pragma("unroll 1") \
    for (int kt = 0; kt < DIMC / 32; kt++) { \
        if (kt + 1 < DIMC / 32) GEMM_LOAD(APTR_BASE, (kt + 1) * 32) \
        GEMM_COMPUTE(kt & 1) \
        if (kt + 1 < DIMC / 32) GEMM_STORE((kt + 1) & 1) \
        __syncthreads(); \
    }

// ---------------- QKV projection GEMM -----------------
// grid = (256, 18); blockIdx.y/6 selects weight; epilogue applies fmap for q,k
// and writes head-major (B,H,N,D).
__global__ __launch_bounds__(256) void qkv_gemm(
    const float* __restrict__ X, const float* __restrict__ Wq,
    const float* __restrict__ Wk, const float* __restrict__ Wv)
{
    GEMM_PROLOG
    int nb   = blockIdx.y;
    int wsel = nb / 6;
    const float* W = (wsel == 0) ? Wq : (wsel == 1 ? Wk : Wv);
    float*       O = (wsel == 0) ? g_q : (wsel == 1 ? g_k : g_v);
    int n0 = (nb % 6) * 128;
    int m0 = blockIdx.x * 128;
    const float* Abase = X + (size_t)(m0 + a_row) * DIMC;

    GEMM_MAINLOOP(Abase)

#pragma unroll
    for (int i = 0; i < 2; i++) {
#pragma unroll
        for (int j = 0; j < 8; j++) {
            int r0 = m0 + wm * 32 + i * 16 + g;
            int c  = n0 + wn * 64 + j * 8 + t * 2;
            int h = c >> 6, d = c & 63;
#pragma unroll
            for (int half = 0; half < 2; half++) {
                int m = half ? r0 + 8 : r0;
                int b = m >> 12, n = m & 4095;
                float v0 = acc[i][j][half * 2 + 0];
                float v1 = acc[i][j][half * 2 + 1];
                if (wsel < 2) { v0 = fmap_f(v0); v1 = fmap_f(v1); }
                float* dst = O + (((size_t)(b * Hh + h) * Nseq + n) * Dh + d);
                dst[0] = v0; dst[1] = v1;
            }
        }
    }
}

// ---------------- final GEMM: g_attn(32768x768) @ Wo + bo -> out ------------
__global__ __launch_bounds__(256) void out_gemm(
    const float* __restrict__ W, const float* __restrict__ bias,
    float* __restrict__ out)
{
    GEMM_PROLOG
    int n0 = blockIdx.y * 128;
    int m0 = blockIdx.x * 128;
    const float* Abase = g_attn + (size_t)(m0 + a_row) * DIMC;

    GEMM_MAINLOOP(Abase)

#pragma unroll
    for (int i = 0; i < 2; i++) {
#pragma unroll
        for (int j = 0; j < 8; j++) {
            int r0 = m0 + wm * 32 + i * 16 + g;
            int c  = n0 + wn * 64 + j * 8 + t * 2;
            float b0 = bias[c], b1 = bias[c + 1];
            out[(size_t)r0 * DIMC + c]           = acc[i][j][0] + b0;
            out[(size_t)r0 * DIMC + c + 1]       = acc[i][j][1] + b1;
            out[(size_t)(r0 + 8) * DIMC + c]     = acc[i][j][2] + b0;
            out[(size_t)(r0 + 8) * DIMC + c + 1] = acc[i][j][3] + b1;
        }
    }
}

// ---------------- vc pooling: mean over 8 consecutive tokens ----------------
__global__ void vpool_kernel()
{
    int idx = blockIdx.x * 256 + threadIdx.x;
    if (idx >= BH * 512 * Dh) return;
    int d   = idx & 63;
    int rest = idx >> 6;
    int n   = rest & 511;
    int bh  = rest >> 9;
    const float* src = g_v + (bh * 4096 + n * 8) * 64 + d;
    float s = 0.0f;
#pragma unroll
    for (int j = 0; j < 8; j++) s += src[j * 64];
    g_vc[idx] = s * 0.125f;
}

// ---------------- kc pooling stage: pool pairs then MLP(LN+gelu) ------------
__global__ __launch_bounds__(256) void pool_mlp(
    int stage,
    const float* __restrict__ pW, const float* __restrict__ pb,
    const float* __restrict__ pg, const float* __restrict__ pbe)
{
    __shared__ float Ws[64][64];
    __shared__ float rows[64][65];
    __shared__ float bs[64], gs[64], bes[64];

    const float* in; float* out; int s_in, s_out;
    if (stage == 0)      { in = g_k;   out = g_kcA; s_in = 4096; s_out = 2048; }
    else if (stage == 1) { in = g_kcA; out = g_kcB; s_in = 2048; s_out = 1024; }
    else                 { in = g_kcB; out = g_kcA; s_in = 1024; s_out = 512;  }
    pW += stage * 4096; pb += stage * 64; pg += stage * 64; pbe += stage * 64;

    int tid = threadIdx.x;
    for (int i = tid; i < 4096; i += 256) Ws[i >> 6][i & 63] = pW[i];
    if (tid < 64) { bs[tid] = pb[tid]; gs[tid] = pg[tid]; bes[tid] = pbe[tid]; }

    int r = tid >> 2, lane4 = tid & 3, c0 = lane4 * 16;
    int rg = blockIdx.x * 64 + r;
    int bh = rg / s_out, n = rg - bh * s_out;
    const float* src = in + (bh * s_in + 2 * n) * 64;
    for (int e = lane4; e < 64; e += 4)
        rows[r][e] = 0.5f * (src[e] + src[64 + e]);
    __syncthreads();

    float y[16];
#pragma unroll
    for (int j = 0; j < 16; j++) y[j] = bs[c0 + j];
    for (int e = 0; e < 64; e++) {
        float xv = rows[r][e];
#pragma unroll
        for (int j = 0; j < 16; j++) y[j] = fmaf(xv, Ws[e][c0 + j], y[j]);
    }
    float s1 = 0.0f, s2 = 0.0f;
#pragma unroll
    for (int j = 0; j < 16; j++) { s1 += y[j]; s2 += y[j] * y[j]; }
    s1 += __shfl_xor_sync(~0u, s1, 1); s2 += __shfl_xor_sync(~0u, s2, 1);
    s1 += __shfl_xor_sync(~0u, s1, 2); s2 += __shfl_xor_sync(~0u, s2, 2);
    float mu  = s1 * (1.0f / 64.0f);
    float var = s2 * (1.0f / 64.0f) - mu * mu;
    float inv = rsqrtf(var + 1e-5f);

    float* orow = out + rg * 64;
#pragma unroll
    for (int j = 0; j < 16; j++) {
        float t = (y[j] - mu) * inv * gs[c0 + j] + bes[c0 + j];
        orow[c0 + j] = gelu_f(t);
    }
}

// ---------------- kv = (kc/sqrt(512))^T vc, plus k_sum, per (b,h) -----------
__global__ __launch_bounds__(256) void kv_kernel()
{
    int bh = blockIdx.x;
    __shared__ float ks[64][65];
    __shared__ float vs[64][65];
    int tid = threadIdx.x;
    int td = tid & 15, te = tid >> 4;
    float acc[4][4];
#pragma unroll
    for (int i = 0; i < 4; i++)
#pragma unroll
        for (int j = 0; j < 4; j++) acc[i][j] = 0.0f;
    float colsum = 0.0f;
    const float scale = rsqrtf(512.0f);

    for (int nt = 0; nt < 512; nt += 64) {
        for (int i = tid; i < 4096; i += 256) {
            int rr = i >> 6, cc = i & 63;
            ks[rr][cc] = g_kcA[(bh * 512 + nt + rr) * 64 + cc] * scale;
            vs[rr][cc] = g_vc [(bh * 512 + nt + rr) * 64 + cc];
        }
        __syncthreads();
        if (tid < 64) {
            for (int rr = 0; rr < 64; rr++) colsum += ks[rr][tid];
        }
#pragma unroll 4
        for (int nn = 0; nn < 64; nn++) {
            float a[4], bb[4];
#pragma unroll
            for (int i = 0; i < 4; i++) a[i]  = ks[nn][td * 4 + i];
#pragma unroll
            for (int j = 0; j < 4; j++) bb[j] = vs[nn][te * 4 + j];
#pragma unroll
            for (int i = 0; i < 4; i++)
#pragma unroll
                for (int j = 0; j < 4; j++)
                    acc[i][j] = fmaf(a[i], bb[j], acc[i][j]);
        }
        __syncthreads();
    }
#pragma unroll
    for (int i = 0; i < 4; i++)
#pragma unroll
        for (int j = 0; j < 4; j++)
            g_kv[(bh * 64 + td * 4 + i) * 64 + te * 4 + j] = acc[i][j];
    if (tid < 64) g_ksum[bh * 64 + tid] = colsum;
}

// ---------------- fused: out=q@kv, /(q.k_sum+1e-6), 3x exp MLP, re-layout ---
__global__ __launch_bounds__(256) void attn_mlp(
    const float* __restrict__ eW, const float* __restrict__ eb,
    const float* __restrict__ eg, const float* __restrict__ ebe)
{
    __shared__ float bufA[64][64];
    __shared__ float rows[64][65];
    __shared__ float ksm[64];
    __shared__ float vb[64], vg[64], vbe[64];

    int bh = blockIdx.x >> 6;
    int n0 = (blockIdx.x & 63) << 6;
    int tid = threadIdx.x;
    int r = tid >> 2, lane4 = tid & 3, c0 = lane4 * 16;

    for (int i = tid; i < 4096; i += 256) bufA[i >> 6][i & 63] = g_kv[bh * 4096 + i];
    if (tid < 64) ksm[tid] = g_ksum[bh * 64 + tid];
    const float* qrow = g_q + (bh * 4096 + n0 + r) * 64;
    for (int e = lane4; e < 64; e += 4) rows[r][e] = qrow[e];
    __syncthreads();

    float y[16];
#pragma unroll
    for (int j = 0; j < 16; j++) y[j] = 0.0f;
    for (int e = 0; e < 64; e++) {
        float qe = rows[r][e];
#pragma unroll
        for (int j = 0; j < 16; j++) y[j] = fmaf(qe, bufA[e][c0 + j], y[j]);
    }
    float dp = 0.0f;
    for (int e = lane4; e < 64; e += 4) dp += rows[r][e] * ksm[e];
    dp += __shfl_xor_sync(~0u, dp, 1);
    dp += __shfl_xor_sync(~0u, dp, 2);
    float inv = 1.0f / (dp + 1e-6f);
    __syncwarp();
#pragma unroll
    for (int j = 0; j < 16; j++) rows[r][c0 + j] = y[j] * inv;

    for (int s = 2; s >= 0; s--) {
        __syncthreads();
        for (int i = tid; i < 4096; i += 256) bufA[i >> 6][i & 63] = eW[s * 4096 + i];
        if (tid < 64) { vb[tid] = eb[s * 64 + tid]; vg[tid] = eg[s * 64 + tid]; vbe[tid] = ebe[s * 64 + tid]; }
        __syncthreads();

        float z[16];
#pragma unroll
        for (int j = 0; j < 16; j++) z[j] = vb[c0 + j];
        for (int e = 0; e < 64; e++) {
            float xv = rows[r][e];
#pragma unroll
            for (int j = 0; j < 16; j++) z[j] = fmaf(xv, bufA[e][c0 + j], z[j]);
        }
        float s1 = 0.0f, s2 = 0.0f;
#pragma unroll
        for (int j = 0; j < 16; j++) { s1 += z[j]; s2 += z[j] * z[j]; }
        s1 += __shfl_xor_sync(~0u, s1, 1); s2 += __shfl_xor_sync(~0u, s2, 1);
        s1 += __shfl_xor_sync(~0u, s1, 2); s2 += __shfl_xor_sync(~0u, s2, 2);
        float mu   = s1 * (1.0f / 64.0f);
        float var  = s2 * (1.0f / 64.0f) - mu * mu;
        float rinv = rsqrtf(var + 1e-5f);
        __syncwarp();
#pragma unroll
        for (int j = 0; j < 16; j++)
            rows[r][c0 + j] = gelu_f((z[j] - mu) * rinv * vg[c0 + j] + vbe[c0 + j]);
    }
    __syncwarp();
    int b = bh / Hh, h = bh % Hh;
    float* orow = g_attn + (b * 4096 + n0 + r) * DIMC + h * 64;
#pragma unroll
    for (int j = 0; j < 16; j++) orow[c0 + j] = rows[r][c0 + j];
}

// ---------------- launch --------------------------------------------------
extern "C" void kernel_launch(void* const* d_in, const int* in_sizes, int n_in,
                              void* d_out, int out_size)
{
    const float* x   = (const float*)d_in[0];
    const float* Wq  = (const float*)d_in[1];
    const float* Wk  = (const float*)d_in[2];
    const float* Wv  = (const float*)d_in[3];
    const float* pW  = (const float*)d_in[4];
    const float* pb  = (const float*)d_in[5];
    const float* pg  = (const float*)d_in[6];
    const float* pbe = (const float*)d_in[7];
    const float* eW  = (const float*)d_in[8];
    const float* eb  = (const float*)d_in[9];
    const float* eg  = (const float*)d_in[10];
    const float* ebe = (const float*)d_in[11];
    const float* Wo  = (const float*)d_in[12];
    const float* bo  = (const float*)d_in[13];
    float* out = (float*)d_out;

    static bool attr_set = false;
    if (!attr_set) {
        cudaFuncSetAttribute(qkv_gemm,
            cudaFuncAttributeMaxDynamicSharedMemorySize, GEMM_SMEM_BYTES);
        cudaFuncSetAttribute(out_gemm,
            cudaFuncAttributeMaxDynamicSharedMemorySize, GEMM_SMEM_BYTES);
        attr_set = true;
    }

    qkv_gemm<<<dim3(MR / 128, 18), 256, GEMM_SMEM_BYTES>>>(x, Wq, Wk, Wv);
    vpool_kernel<<<(BH * 512 * Dh + 255) / 256, 256>>>();
    pool_mlp<<<BH * 2048 / 64, 256>>>(0, pW, pb, pg, pbe);
    pool_mlp<<<BH * 1024 / 64, 256>>>(1, pW, pb, pg, pbe);
    pool_mlp<<<BH * 512 / 64, 256>>>(2, pW, pb, pg, pbe);
    kv_kernel<<<BH, 256>>>();
    attn_mlp<<<BH * 64, 256>>>(eW, eb, eg, ebe);
    out_gemm<<<dim3(MR / 128, 6), 256, GEMM_SMEM_BYTES>>>(Wo, bo, out);
}

// round 4
// speedup vs baseline: 1.6485x; 1.0055x over previous
#include <cuda_runtime.h>
#include <math.h>
#include <stdint.h>

#define Bz   8
#define Nseq 4096
#define DIMC 768
#define Hh   12
#define Dh   64
#define BH   (Bz*Hh)        // 96
#define MR   (Bz*Nseq)      // 32768

// ---------------- scratch (device globals; no allocations allowed) ----------
__device__ float g_q[BH*Nseq*Dh];
__device__ float g_k[BH*Nseq*Dh];
__device__ float g_v[BH*Nseq*Dh];
__device__ float g_kcA[BH*2048*Dh];
__device__ float g_kcB[BH*1024*Dh];
__device__ float g_vc[BH*512*Dh];
__device__ float g_kv[BH*Dh*Dh];
__device__ float g_ksum[BH*Dh];
__device__ float g_attn[MR*DIMC];

__device__ __forceinline__ float gelu_f(float t) {
    return 0.5f * t * (1.0f + erff(t * 0.70710678118654752f));
}
__device__ __forceinline__ float fmap_f(float t) {   // elu(t)+1
    return t > 0.0f ? t + 1.0f : expf(t);
}
__device__ __forceinline__ uint32_t f2tf32(float f) {
    uint32_t r;
    asm("cvt.rna.tf32.f32 %0, %1;" : "=r"(r) : "f"(f));
    return r;
}
__device__ __forceinline__ void mma_tf32(float c[4],
    uint32_t a0, uint32_t a1, uint32_t a2, uint32_t a3,
    uint32_t b0, uint32_t b1)
{
    asm volatile(
        "mma.sync.aligned.m16n8k8.row.col.f32.tf32.tf32.f32 "
        "{%0,%1,%2,%3}, {%4,%5,%6,%7}, {%8,%9}, {%0,%1,%2,%3};"
        : "+f"(c[0]), "+f"(c[1]), "+f"(c[2]), "+f"(c[3])
        : "r"(a0), "r"(a1), "r"(a2), "r"(a3), "r"(b0), "r"(b1));
}
__device__ __forceinline__ void cp_async16(uint32_t dst, const void* src) {
    asm volatile("cp.async.cg.shared.global [%0], [%1], 16;" :: "r"(dst), "l"(src));
}

// =======================================================================
// Tensor-core tf32 GEMM, cp.async double-buffered, 2 CTAs/SM.
// C[128x128] tile of A(Mx768) @ W(768x768); 8 warps = 4(M) x 2(N);
// warp tile 32x64; BK=32. Smem holds raw f32; cvt to tf32 at fragment load.
// =======================================================================
#define AS_STRIDE 36
#define BS_STRIDE 136
#define AS_TILE   (128 * AS_STRIDE)
#define BS_TILE   (32 * BS_STRIDE)
#define NT        (DIMC / 32)
#define GEMM_SMEM_BYTES ((2 * AS_TILE + 2 * BS_TILE) * 4)

#define GEMM_PROLOG \
    extern __shared__ float smemg[]; \
    float* Asf = smemg; \
    float* Bsf = smemg + 2 * AS_TILE; \
    uint32_t As_base = (uint32_t)__cvta_generic_to_shared(Asf); \
    uint32_t Bs_base = (uint32_t)__cvta_generic_to_shared(Bsf); \
    int tid = threadIdx.x; \
    int warp = tid >> 5, lane = tid & 31; \
    int g = lane >> 2, t = lane & 3; \
    int wm = warp >> 1, wn = warp & 1; \
    int a_row = tid >> 1, a_col = (tid & 1) << 4; \
    int b_row = tid >> 3, b_col = (tid & 7) << 4; \
    float acc[2][8][4]; \
    _Pragma("unroll") \
    for (int i = 0; i < 2; i++) \
        _Pragma("unroll") \
        for (int j = 0; j < 8; j++) \
            _Pragma("unroll") \
            for (int q = 0; q < 4; q++) acc[i][j][q] = 0.0f;

#define GEMM_CPLOAD(APTR_BASE, K0, BUF) { \
    const float* ap_ = (APTR_BASE) + (K0) + a_col; \
    const float* bp_ = W + (size_t)((K0) + b_row) * DIMC + n0 + b_col; \
    uint32_t asd = As_base + (uint32_t)(((BUF) * AS_TILE + a_row * AS_STRIDE + a_col) * 4); \
    uint32_t bsd = Bs_base + (uint32_t)(((BUF) * BS_TILE + b_row * BS_STRIDE + b_col) * 4); \
    _Pragma("unroll") \
    for (int u = 0; u < 4; u++) { \
        cp_async16(asd + u * 16, ap_ + u * 4); \
        cp_async16(bsd + u * 16, bp_ + u * 4); \
    } }

#define GEMM_COMPUTE(BUF) { \
    const float* Asc = Asf + (BUF) * AS_TILE; \
    const float* Bsc = Bsf + (BUF) * BS_TILE; \
    _Pragma("unroll") \
    for (int kk = 0; kk < 4; kk++) { \
        int ks = kk * 8; \
        uint32_t af[2][4]; \
        _Pragma("unroll") \
        for (int i = 0; i < 2; i++) { \
            int rb = wm * 32 + i * 16; \
            af[i][0] = f2tf32(Asc[(rb + g    ) * AS_STRIDE + ks + t    ]); \
            af[i][1] = f2tf32(Asc[(rb + g + 8) * AS_STRIDE + ks + t    ]); \
            af[i][2] = f2tf32(Asc[(rb + g    ) * AS_STRIDE + ks + t + 4]); \
            af[i][3] = f2tf32(Asc[(rb + g + 8) * AS_STRIDE + ks + t + 4]); \
        } \
        uint32_t bf[8][2]; \
        _Pragma("unroll") \
        for (int j = 0; j < 8; j++) { \
            int cb = wn * 64 + j * 8 + g; \
            bf[j][0] = f2tf32(Bsc[(ks + t    ) * BS_STRIDE + cb]); \
            bf[j][1] = f2tf32(Bsc[(ks + t + 4) * BS_STRIDE + cb]); \
        } \
        _Pragma("unroll") \
        for (int i = 0; i < 2; i++) \
            _Pragma("unroll") \
            for (int j = 0; j < 8; j++) \
                mma_tf32(acc[i][j], af[i][0], af[i][1], af[i][2], af[i][3], \
                         bf[j][0], bf[j][1]); \
    } }

#define GEMM_MAINLOOP(APTR_BASE) \
    GEMM_CPLOAD(APTR_BASE, 0, 0) \
    asm volatile("cp.async.commit_group;"); \
    _Pragma("unroll 1") \
    for (int kt = 0; kt < NT; kt++) { \
        if (kt + 1 < NT) { \
            GEMM_CPLOAD(APTR_BASE, (kt + 1) * 32, (kt + 1) & 1) \
            asm volatile("cp.async.commit_group;"); \
            asm volatile("cp.async.wait_group 1;"); \
        } else { \
            asm volatile("cp.async.wait_group 0;"); \
        } \
        __syncthreads(); \
        GEMM_COMPUTE(kt & 1) \
        __syncthreads(); \
    }

// ---------------- QKV projection GEMM -----------------
// grid = (256, 18); blockIdx.y/6 selects weight; epilogue applies fmap for q,k
// and writes head-major (B,H,N,D).
__global__ __launch_bounds__(256, 2) void qkv_gemm(
    const float* __restrict__ X, const float* __restrict__ Wq,
    const float* __restrict__ Wk, const float* __restrict__ Wv)
{
    GEMM_PROLOG
    int nb   = blockIdx.y;
    int wsel = nb / 6;
    const float* W = (wsel == 0) ? Wq : (wsel == 1 ? Wk : Wv);
    float*       O = (wsel == 0) ? g_q : (wsel == 1 ? g_k : g_v);
    int n0 = (nb % 6) * 128;
    int m0 = blockIdx.x * 128;
    const float* Abase = X + (size_t)(m0 + a_row) * DIMC;

    GEMM_MAINLOOP(Abase)

#pragma unroll
    for (int i = 0; i < 2; i++) {
#pragma unroll
        for (int j = 0; j < 8; j++) {
            int r0 = m0 + wm * 32 + i * 16 + g;
            int c  = n0 + wn * 64 + j * 8 + t * 2;
            int h = c >> 6, d = c & 63;
#pragma unroll
            for (int half = 0; half < 2; half++) {
                int m = half ? r0 + 8 : r0;
                int b = m >> 12, n = m & 4095;
                float v0 = acc[i][j][half * 2 + 0];
                float v1 = acc[i][j][half * 2 + 1];
                if (wsel < 2) { v0 = fmap_f(v0); v1 = fmap_f(v1); }
                float* dst = O + (((size_t)(b * Hh + h) * Nseq + n) * Dh + d);
                dst[0] = v0; dst[1] = v1;
            }
        }
    }
}

// ---------------- final GEMM: g_attn(32768x768) @ Wo + bo -> out ------------
__global__ __launch_bounds__(256, 2) void out_gemm(
    const float* __restrict__ W, const float* __restrict__ bias,
    float* __restrict__ out)
{
    GEMM_PROLOG
    int n0 = blockIdx.y * 128;
    int m0 = blockIdx.x * 128;
    const float* Abase = g_attn + (size_t)(m0 + a_row) * DIMC;

    GEMM_MAINLOOP(Abase)

#pragma unroll
    for (int i = 0; i < 2; i++) {
#pragma unroll
        for (int j = 0; j < 8; j++) {
            int r0 = m0 + wm * 32 + i * 16 + g;
            int c  = n0 + wn * 64 + j * 8 + t * 2;
            float b0 = bias[c], b1 = bias[c + 1];
            out[(size_t)r0 * DIMC + c]           = acc[i][j][0] + b0;
            out[(size_t)r0 * DIMC + c + 1]       = acc[i][j][1] + b1;
            out[(size_t)(r0 + 8) * DIMC + c]     = acc[i][j][2] + b0;
            out[(size_t)(r0 + 8) * DIMC + c + 1] = acc[i][j][3] + b1;
        }
    }
}

// ---------------- vc pooling: mean over 8 consecutive tokens ----------------
__global__ void vpool_kernel()
{
    int idx = blockIdx.x * 256 + threadIdx.x;
    if (idx >= BH * 512 * Dh) return;
    int d   = idx & 63;
    int rest = idx >> 6;
    int n   = rest & 511;
    int bh  = rest >> 9;
    const float* src = g_v + (bh * 4096 + n * 8) * 64 + d;
    float s = 0.0f;
#pragma unroll
    for (int j = 0; j < 8; j++) s += src[j * 64];
    g_vc[idx] = s * 0.125f;
}

// ---------------- kc pooling stage: pool pairs then MLP(LN+gelu) ------------
__global__ __launch_bounds__(256) void pool_mlp(
    int stage,
    const float* __restrict__ pW, const float* __restrict__ pb,
    const float* __restrict__ pg, const float* __restrict__ pbe)
{
    __shared__ float Ws[64][64];
    __shared__ float rows[64][65];
    __shared__ float bs[64], gs[64], bes[64];

    const float* in; float* out; int s_in, s_out;
    if (stage == 0)      { in = g_k;   out = g_kcA; s_in = 4096; s_out = 2048; }
    else if (stage == 1) { in = g_kcA; out = g_kcB; s_in = 2048; s_out = 1024; }
    else                 { in = g_kcB; out = g_kcA; s_in = 1024; s_out = 512;  }
    pW += stage * 4096; pb += stage * 64; pg += stage * 64; pbe += stage * 64;

    int tid = threadIdx.x;
    for (int i = tid; i < 4096; i += 256) Ws[i >> 6][i & 63] = pW[i];
    if (tid < 64) { bs[tid] = pb[tid]; gs[tid] = pg[tid]; bes[tid] = pbe[tid]; }

    int r = tid >> 2, lane4 = tid & 3, c0 = lane4 * 16;
    int rg = blockIdx.x * 64 + r;
    int bh = rg / s_out, n = rg - bh * s_out;
    const float* src = in + (bh * s_in + 2 * n) * 64;
    for (int e = lane4; e < 64; e += 4)
        rows[r][e] = 0.5f * (src[e] + src[64 + e]);
    __syncthreads();

    float y[16];
#pragma unroll
    for (int j = 0; j < 16; j++) y[j] = bs[c0 + j];
    for (int e = 0; e < 64; e++) {
        float xv = rows[r][e];
#pragma unroll
        for (int j = 0; j < 16; j++) y[j] = fmaf(xv, Ws[e][c0 + j], y[j]);
    }
    float s1 = 0.0f, s2 = 0.0f;
#pragma unroll
    for (int j = 0; j < 16; j++) { s1 += y[j]; s2 += y[j] * y[j]; }
    s1 += __shfl_xor_sync(~0u, s1, 1); s2 += __shfl_xor_sync(~0u, s2, 1);
    s1 += __shfl_xor_sync(~0u, s1, 2); s2 += __shfl_xor_sync(~0u, s2, 2);
    float mu  = s1 * (1.0f / 64.0f);
    float var = s2 * (1.0f / 64.0f) - mu * mu;
    float inv = rsqrtf(var + 1e-5f);

    float* orow = out + rg * 64;
#pragma unroll
    for (int j = 0; j < 16; j++) {
        float t = (y[j] - mu) * inv * gs[c0 + j] + bes[c0 + j];
        orow[c0 + j] = gelu_f(t);
    }
}

// ---------------- kv = (kc/sqrt(512))^T vc, plus k_sum, per (b,h) -----------
__global__ __launch_bounds__(256) void kv_kernel()
{
    int bh = blockIdx.x;
    __shared__ float ks[64][65];
    __shared__ float vs[64][65];
    int tid = threadIdx.x;
    int td = tid & 15, te = tid >> 4;
    float acc[4][4];
#pragma unroll
    for (int i = 0; i < 4; i++)
#pragma unroll
        for (int j = 0; j < 4; j++) acc[i][j] = 0.0f;
    float colsum = 0.0f;
    const float scale = rsqrtf(512.0f);

    for (int nt = 0; nt < 512; nt += 64) {
        for (int i = tid; i < 4096; i += 256) {
            int rr = i >> 6, cc = i & 63;
            ks[rr][cc] = g_kcA[(bh * 512 + nt + rr) * 64 + cc] * scale;
            vs[rr][cc] = g_vc [(bh * 512 + nt + rr) * 64 + cc];
        }
        __syncthreads();
        if (tid < 64) {
            for (int rr = 0; rr < 64; rr++) colsum += ks[rr][tid];
        }
#pragma unroll 4
        for (int nn = 0; nn < 64; nn++) {
            float a[4], bb[4];
#pragma unroll
            for (int i = 0; i < 4; i++) a[i]  = ks[nn][td * 4 + i];
#pragma unroll
            for (int j = 0; j < 4; j++) bb[j] = vs[nn][te * 4 + j];
#pragma unroll
            for (int i = 0; i < 4; i++)
#pragma unroll
                for (int j = 0; j < 4; j++)
                    acc[i][j] = fmaf(a[i], bb[j], acc[i][j]);
        }
        __syncthreads();
    }
#pragma unroll
    for (int i = 0; i < 4; i++)
#pragma unroll
        for (int j = 0; j < 4; j++)
            g_kv[(bh * 64 + td * 4 + i) * 64 + te * 4 + j] = acc[i][j];
    if (tid < 64) g_ksum[bh * 64 + tid] = colsum;
}

// ---------------- fused: out=q@kv, /(q.k_sum+1e-6), 3x exp MLP, re-layout ---
__global__ __launch_bounds__(256) void attn_mlp(
    const float* __restrict__ eW, const float* __restrict__ eb,
    const float* __restrict__ eg, const float* __restrict__ ebe)
{
    __shared__ float bufA[64][64];
    __shared__ float rows[64][65];
    __shared__ float ksm[64];
    __shared__ float vb[64], vg[64], vbe[64];

    int bh = blockIdx.x >> 6;
    int n0 = (blockIdx.x & 63) << 6;
    int tid = threadIdx.x;
    int r = tid >> 2, lane4 = tid & 3, c0 = lane4 * 16;

    for (int i = tid; i < 4096; i += 256) bufA[i >> 6][i & 63] = g_kv[bh * 4096 + i];
    if (tid < 64) ksm[tid] = g_ksum[bh * 64 + tid];
    const float* qrow = g_q + (bh * 4096 + n0 + r) * 64;
    for (int e = lane4; e < 64; e += 4) rows[r][e] = qrow[e];
    __syncthreads();

    float y[16];
#pragma unroll
    for (int j = 0; j < 16; j++) y[j] = 0.0f;
    for (int e = 0; e < 64; e++) {
        float qe = rows[r][e];
#pragma unroll
        for (int j = 0; j < 16; j++) y[j] = fmaf(qe, bufA[e][c0 + j], y[j]);
    }
    float dp = 0.0f;
    for (int e = lane4; e < 64; e += 4) dp += rows[r][e] * ksm[e];
    dp += __shfl_xor_sync(~0u, dp, 1);
    dp += __shfl_xor_sync(~0u, dp, 2);
    float inv = 1.0f / (dp + 1e-6f);
    __syncwarp();
#pragma unroll
    for (int j = 0; j < 16; j++) rows[r][c0 + j] = y[j] * inv;

    for (int s = 2; s >= 0; s--) {
        __syncthreads();
        for (int i = tid; i < 4096; i += 256) bufA[i >> 6][i & 63] = eW[s * 4096 + i];
        if (tid < 64) { vb[tid] = eb[s * 64 + tid]; vg[tid] = eg[s * 64 + tid]; vbe[tid] = ebe[s * 64 + tid]; }
        __syncthreads();

        float z[16];
#pragma unroll
        for (int j = 0; j < 16; j++) z[j] = vb[c0 + j];
        for (int e = 0; e < 64; e++) {
            float xv = rows[r][e];
#pragma unroll
            for (int j = 0; j < 16; j++) z[j] = fmaf(xv, bufA[e][c0 + j], z[j]);
        }
        float s1 = 0.0f, s2 = 0.0f;
#pragma unroll
        for (int j = 0; j < 16; j++) { s1 += z[j]; s2 += z[j] * z[j]; }
        s1 += __shfl_xor_sync(~0u, s1, 1); s2 += __shfl_xor_sync(~0u, s2, 1);
        s1 += __shfl_xor_sync(~0u, s1, 2); s2 += __shfl_xor_sync(~0u, s2, 2);
        float mu   = s1 * (1.0f / 64.0f);
        float var  = s2 * (1.0f / 64.0f) - mu * mu;
        float rinv = rsqrtf(var + 1e-5f);
        __syncwarp();
#pragma unroll
        for (int j = 0; j < 16; j++)
            rows[r][c0 + j] = gelu_f((z[j] - mu) * rinv * vg[c0 + j] + vbe[c0 + j]);
    }
    __syncwarp();
    int b = bh / Hh, h = bh % Hh;
    float* orow = g_attn + (b * 4096 + n0 + r) * DIMC + h * 64;
#pragma unroll
    for (int j = 0; j < 16; j++) orow[c0 + j] = rows[r][c0 + j];
}

// ---------------- launch --------------------------------------------------
extern "C" void kernel_launch(void* const* d_in, const int* in_sizes, int n_in,
                              void* d_out, int out_size)
{
    const float* x   = (const float*)d_in[0];
    const float* Wq  = (const float*)d_in[1];
    const float* Wk  = (const float*)d_in[2];
    const float* Wv  = (const float*)d_in[3];
    const float* pW  = (const float*)d_in[4];
    const float* pb  = (const float*)d_in[5];
    const float* pg  = (const float*)d_in[6];
    const float* pbe = (const float*)d_in[7];
    const float* eW  = (const float*)d_in[8];
    const float* eb  = (const float*)d_in[9];
    const float* eg  = (const float*)d_in[10];
    const float* ebe = (const float*)d_in[11];
    const float* Wo  = (const float*)d_in[12];
    const float* bo  = (const float*)d_in[13];
    float* out = (float*)d_out;

    cudaFuncSetAttribute(qkv_gemm,
        cudaFuncAttributeMaxDynamicSharedMemorySize, GEMM_SMEM_BYTES);
    cudaFuncSetAttribute(out_gemm,
        cudaFuncAttributeMaxDynamicSharedMemorySize, GEMM_SMEM_BYTES);

    qkv_gemm<<<dim3(MR / 128, 18), 256, GEMM_SMEM_BYTES>>>(x, Wq, Wk, Wv);
    vpool_kernel<<<(BH * 512 * Dh + 255) / 256, 256>>>();
    pool_mlp<<<BH * 2048 / 64, 256>>>(0, pW, pb, pg, pbe);
    pool_mlp<<<BH * 1024 / 64, 256>>>(1, pW, pb, pg, pbe);
    pool_mlp<<<BH * 512 / 64, 256>>>(2, pW, pb, pg, pbe);
    kv_kernel<<<BH, 256>>>();
    attn_mlp<<<BH * 64, 256>>>(eW, eb, eg, ebe);
    out_gemm<<<dim3(MR / 128, 6), 256, GEMM_SMEM_BYTES>>>(Wo, bo, out);
}

// round 5
// speedup vs baseline: 2.5631x; 1.5548x over previous
#include <cuda_runtime.h>
#include <math.h>
#include <stdint.h>

#define Bz   8
#define Nseq 4096
#define DIMC 768
#define Hh   12
#define Dh   64
#define BH   (Bz*Hh)        // 96
#define MR   (Bz*Nseq)      // 32768

// ---------------- scratch (device globals; no allocations allowed) ----------
__device__ float g_q[BH*Nseq*Dh];
__device__ float g_k[BH*Nseq*Dh];
__device__ float g_v[BH*Nseq*Dh];
__device__ float g_kcA[BH*2048*Dh];
__device__ float g_kcB[BH*1024*Dh];
__device__ float g_vc[BH*512*Dh];
__device__ float g_kv[BH*Dh*Dh];
__device__ float g_ksum[BH*Dh];
__device__ float g_attn[MR*DIMC];

__device__ __forceinline__ float gelu_f(float t) {
    return 0.5f * t * (1.0f + erff(t * 0.70710678118654752f));
}
__device__ __forceinline__ float fmap_f(float t) {   // elu(t)+1
    return t > 0.0f ? t + 1.0f : expf(t);
}
__device__ __forceinline__ uint32_t f2tf32(float f) {
    uint32_t r;
    asm("cvt.rna.tf32.f32 %0, %1;" : "=r"(r) : "f"(f));
    return r;
}
__device__ __forceinline__ void split_tf32(float x, uint32_t& hi, uint32_t& lo) {
    hi = f2tf32(x);
    lo = f2tf32(x - __uint_as_float(hi));
}
__device__ __forceinline__ void mma_tf32(float c[4],
    uint32_t a0, uint32_t a1, uint32_t a2, uint32_t a3,
    uint32_t b0, uint32_t b1)
{
    asm volatile(
        "mma.sync.aligned.m16n8k8.row.col.f32.tf32.tf32.f32 "
        "{%0,%1,%2,%3}, {%4,%5,%6,%7}, {%8,%9}, {%0,%1,%2,%3};"
        : "+f"(c[0]), "+f"(c[1]), "+f"(c[2]), "+f"(c[3])
        : "r"(a0), "r"(a1), "r"(a2), "r"(a3), "r"(b0), "r"(b1));
}
__device__ __forceinline__ void cp_async16(uint32_t dst, const void* src) {
    asm volatile("cp.async.cg.shared.global [%0], [%1], 16;" :: "r"(dst), "l"(src));
}

// =======================================================================
// Big GEMMs (unchanged from R4): tf32, cp.async double-buffered.
// =======================================================================
#define AS_STRIDE 36
#define BS_STRIDE 136
#define AS_TILE   (128 * AS_STRIDE)
#define BS_TILE   (32 * BS_STRIDE)
#define NT        (DIMC / 32)
#define GEMM_SMEM_BYTES ((2 * AS_TILE + 2 * BS_TILE) * 4)

#define GEMM_PROLOG \
    extern __shared__ float smemg[]; \
    float* Asf = smemg; \
    float* Bsf = smemg + 2 * AS_TILE; \
    uint32_t As_base = (uint32_t)__cvta_generic_to_shared(Asf); \
    uint32_t Bs_base = (uint32_t)__cvta_generic_to_shared(Bsf); \
    int tid = threadIdx.x; \
    int warp = tid >> 5, lane = tid & 31; \
    int g = lane >> 2, t = lane & 3; \
    int wm = warp >> 1, wn = warp & 1; \
    int a_row = tid >> 1, a_col = (tid & 1) << 4; \
    int b_row = tid >> 3, b_col = (tid & 7) << 4; \
    float acc[2][8][4]; \
    _Pragma("unroll") \
    for (int i = 0; i < 2; i++) \
        _Pragma("unroll") \
        for (int j = 0; j < 8; j++) \
            _Pragma("unroll") \
            for (int q = 0; q < 4; q++) acc[i][j][q] = 0.0f;

#define GEMM_CPLOAD(APTR_BASE, K0, BUF) { \
    const float* ap_ = (APTR_BASE) + (K0) + a_col; \
    const float* bp_ = W + (size_t)((K0) + b_row) * DIMC + n0 + b_col; \
    uint32_t asd = As_base + (uint32_t)(((BUF) * AS_TILE + a_row * AS_STRIDE + a_col) * 4); \
    uint32_t bsd = Bs_base + (uint32_t)(((BUF) * BS_TILE + b_row * BS_STRIDE + b_col) * 4); \
    _Pragma("unroll") \
    for (int u = 0; u < 4; u++) { \
        cp_async16(asd + u * 16, ap_ + u * 4); \
        cp_async16(bsd + u * 16, bp_ + u * 4); \
    } }

#define GEMM_COMPUTE(BUF) { \
    const float* Asc = Asf + (BUF) * AS_TILE; \
    const float* Bsc = Bsf + (BUF) * BS_TILE; \
    _Pragma("unroll") \
    for (int kk = 0; kk < 4; kk++) { \
        int ks = kk * 8; \
        uint32_t af[2][4]; \
        _Pragma("unroll") \
        for (int i = 0; i < 2; i++) { \
            int rb = wm * 32 + i * 16; \
            af[i][0] = f2tf32(Asc[(rb + g    ) * AS_STRIDE + ks + t    ]); \
            af[i][1] = f2tf32(Asc[(rb + g + 8) * AS_STRIDE + ks + t    ]); \
            af[i][2] = f2tf32(Asc[(rb + g    ) * AS_STRIDE + ks + t + 4]); \
            af[i][3] = f2tf32(Asc[(rb + g + 8) * AS_STRIDE + ks + t + 4]); \
        } \
        uint32_t bf[8][2]; \
        _Pragma("unroll") \
        for (int j = 0; j < 8; j++) { \
            int cb = wn * 64 + j * 8 + g; \
            bf[j][0] = f2tf32(Bsc[(ks + t    ) * BS_STRIDE + cb]); \
            bf[j][1] = f2tf32(Bsc[(ks + t + 4) * BS_STRIDE + cb]); \
        } \
        _Pragma("unroll") \
        for (int i = 0; i < 2; i++) \
            _Pragma("unroll") \
            for (int j = 0; j < 8; j++) \
                mma_tf32(acc[i][j], af[i][0], af[i][1], af[i][2], af[i][3], \
                         bf[j][0], bf[j][1]); \
    } }

#define GEMM_MAINLOOP(APTR_BASE) \
    GEMM_CPLOAD(APTR_BASE, 0, 0) \
    asm volatile("cp.async.commit_group;"); \
    _Pragma("unroll 1") \
    for (int kt = 0; kt < NT; kt++) { \
        if (kt + 1 < NT) { \
            GEMM_CPLOAD(APTR_BASE, (kt + 1) * 32, (kt + 1) & 1) \
            asm volatile("cp.async.commit_group;"); \
            asm volatile("cp.async.wait_group 1;"); \
        } else { \
            asm volatile("cp.async.wait_group 0;"); \
        } \
        __syncthreads(); \
        GEMM_COMPUTE(kt & 1) \
        __syncthreads(); \
    }

__global__ __launch_bounds__(256, 2) void qkv_gemm(
    const float* __restrict__ X, const float* __restrict__ Wq,
    const float* __restrict__ Wk, const float* __restrict__ Wv)
{
    GEMM_PROLOG
    int nb   = blockIdx.y;
    int wsel = nb / 6;
    const float* W = (wsel == 0) ? Wq : (wsel == 1 ? Wk : Wv);
    float*       O = (wsel == 0) ? g_q : (wsel == 1 ? g_k : g_v);
    int n0 = (nb % 6) * 128;
    int m0 = blockIdx.x * 128;
    const float* Abase = X + (size_t)(m0 + a_row) * DIMC;

    GEMM_MAINLOOP(Abase)

#pragma unroll
    for (int i = 0; i < 2; i++) {
#pragma unroll
        for (int j = 0; j < 8; j++) {
            int r0 = m0 + wm * 32 + i * 16 + g;
            int c  = n0 + wn * 64 + j * 8 + t * 2;
            int h = c >> 6, d = c & 63;
#pragma unroll
            for (int half = 0; half < 2; half++) {
                int m = half ? r0 + 8 : r0;
                int b = m >> 12, n = m & 4095;
                float v0 = acc[i][j][half * 2 + 0];
                float v1 = acc[i][j][half * 2 + 1];
                if (wsel < 2) { v0 = fmap_f(v0); v1 = fmap_f(v1); }
                float* dst = O + (((size_t)(b * Hh + h) * Nseq + n) * Dh + d);
                dst[0] = v0; dst[1] = v1;
            }
        }
    }
}

__global__ __launch_bounds__(256, 2) void out_gemm(
    const float* __restrict__ W, const float* __restrict__ bias,
    float* __restrict__ out)
{
    GEMM_PROLOG
    int n0 = blockIdx.y * 128;
    int m0 = blockIdx.x * 128;
    const float* Abase = g_attn + (size_t)(m0 + a_row) * DIMC;

    GEMM_MAINLOOP(Abase)

#pragma unroll
    for (int i = 0; i < 2; i++) {
#pragma unroll
        for (int j = 0; j < 8; j++) {
            int r0 = m0 + wm * 32 + i * 16 + g;
            int c  = n0 + wn * 64 + j * 8 + t * 2;
            float b0 = bias[c], b1 = bias[c + 1];
            out[(size_t)r0 * DIMC + c]           = acc[i][j][0] + b0;
            out[(size_t)r0 * DIMC + c + 1]       = acc[i][j][1] + b1;
            out[(size_t)(r0 + 8) * DIMC + c]     = acc[i][j][2] + b0;
            out[(size_t)(r0 + 8) * DIMC + c + 1] = acc[i][j][3] + b1;
        }
    }
}

// =======================================================================
// Tensor-core 64-wide MLP machinery (split-tf32, ~fp32 accuracy).
// Block = 256 rows x 64 cols, K=64. 8 warps, each owns 32 rows (warp-
// private activations in smem). 3 MMAs per logical MMA: Ah*Bh+Al*Bh+Ah*Bl.
// =======================================================================
#define XS_STRIDE 68
#define WS_STRIDE 72
#define MLP_SMEM_BYTES ((256*XS_STRIDE + 64*WS_STRIDE + 4*64) * 4)

__device__ __forceinline__ void mma_block64(
    float acc[2][8][4], const float* Xw, const float* Ws, int g, int t)
{
#pragma unroll
    for (int ks8 = 0; ks8 < 8; ks8++) {
        int ks = ks8 * 8;
        uint32_t aHi[2][4], aLo[2][4];
#pragma unroll
        for (int i = 0; i < 2; i++) {
            const float* xr = Xw + (i * 16 + g) * XS_STRIDE + ks;
            split_tf32(xr[t],                     aHi[i][0], aLo[i][0]);
            split_tf32(xr[8 * XS_STRIDE + t],     aHi[i][1], aLo[i][1]);
            split_tf32(xr[t + 4],                 aHi[i][2], aLo[i][2]);
            split_tf32(xr[8 * XS_STRIDE + t + 4], aHi[i][3], aLo[i][3]);
        }
#pragma unroll
        for (int j = 0; j < 8; j++) {
            int cb = j * 8 + g;
            uint32_t bh0, bl0, bh1, bl1;
            split_tf32(Ws[(ks + t    ) * WS_STRIDE + cb], bh0, bl0);
            split_tf32(Ws[(ks + t + 4) * WS_STRIDE + cb], bh1, bl1);
#pragma unroll
            for (int i = 0; i < 2; i++) {
                mma_tf32(acc[i][j], aHi[i][0], aHi[i][1], aHi[i][2], aHi[i][3], bh0, bh1);
                mma_tf32(acc[i][j], aLo[i][0], aLo[i][1], aLo[i][2], aLo[i][3], bh0, bh1);
                mma_tf32(acc[i][j], aHi[i][0], aHi[i][1], aHi[i][2], aHi[i][3], bl0, bl1);
            }
        }
    }
}

// bias + LN + gelu entirely in registers (quad shuffles for row stats)
__device__ __forceinline__ void ln_gelu_regs(
    float acc[2][8][4], const float* Pb, const float* Pg, const float* Pe, int t)
{
#pragma unroll
    for (int i = 0; i < 2; i++) {
        float s1A = 0, s2A = 0, s1B = 0, s2B = 0;
#pragma unroll
        for (int j = 0; j < 8; j++) {
#pragma unroll
            for (int q = 0; q < 4; q++) {
                int col = j * 8 + t * 2 + (q & 1);
                float v = acc[i][j][q] + Pb[col];
                acc[i][j][q] = v;
                if (q < 2) { s1A += v; s2A += v * v; }
                else       { s1B += v; s2B += v * v; }
            }
        }
        s1A += __shfl_xor_sync(~0u, s1A, 1); s2A += __shfl_xor_sync(~0u, s2A, 1);
        s1B += __shfl_xor_sync(~0u, s1B, 1); s2B += __shfl_xor_sync(~0u, s2B, 1);
        s1A += __shfl_xor_sync(~0u, s1A, 2); s2A += __shfl_xor_sync(~0u, s2A, 2);
        s1B += __shfl_xor_sync(~0u, s1B, 2); s2B += __shfl_xor_sync(~0u, s2B, 2);
        float muA = s1A * (1.0f / 64.0f);
        float muB = s1B * (1.0f / 64.0f);
        float rA = rsqrtf(s2A * (1.0f / 64.0f) - muA * muA + 1e-5f);
        float rB = rsqrtf(s2B * (1.0f / 64.0f) - muB * muB + 1e-5f);
#pragma unroll
        for (int j = 0; j < 8; j++) {
#pragma unroll
            for (int q = 0; q < 4; q++) {
                int col = j * 8 + t * 2 + (q & 1);
                float mu = (q < 2) ? muA : muB;
                float rv = (q < 2) ? rA : rB;
                acc[i][j][q] = gelu_f((acc[i][j][q] - mu) * rv * Pg[col] + Pe[col]);
            }
        }
    }
}

// ---------------- pool stage (tensor core): pair-mean + MLP(LN+gelu) --------
__global__ __launch_bounds__(256) void pool_mlp_tc(
    int stage,
    const float* __restrict__ pW, const float* __restrict__ pb,
    const float* __restrict__ pg, const float* __restrict__ pbe)
{
    extern __shared__ float sm[];
    float* Xs = sm;
    float* Ws = sm + 256 * XS_STRIDE;
    float* Pb = Ws + 64 * WS_STRIDE;
    float* Pg = Pb + 64;
    float* Pe = Pg + 64;

    const float* in; float* out; int s_in, s_out;
    if (stage == 0)      { in = g_k;   out = g_kcA; s_in = 4096; s_out = 2048; }
    else if (stage == 1) { in = g_kcA; out = g_kcB; s_in = 2048; s_out = 1024; }
    else                 { in = g_kcB; out = g_kcA; s_in = 1024; s_out = 512;  }

    int tid = threadIdx.x, warp = tid >> 5, lane = tid & 31;
    int g = lane >> 2, t = lane & 3;

    // pooled activation load: X row = mean of input rows 2n, 2n+1
    for (int idx = tid; idx < 256 * 16; idx += 256) {
        int r = idx >> 4, c4 = (idx & 15) << 2;
        int rg = blockIdx.x * 256 + r;
        int bh = rg / s_out, n = rg - bh * s_out;
        const float* src = in + ((size_t)bh * s_in + 2 * n) * 64 + c4;
        float4 a = *(const float4*)src;
        float4 b = *(const float4*)(src + 64);
        float4 v;
        v.x = 0.5f * (a.x + b.x); v.y = 0.5f * (a.y + b.y);
        v.z = 0.5f * (a.z + b.z); v.w = 0.5f * (a.w + b.w);
        *(float4*)&Xs[r * XS_STRIDE + c4] = v;
    }
    for (int idx = tid; idx < 4096; idx += 256)
        Ws[(idx >> 6) * WS_STRIDE + (idx & 63)] = pW[stage * 4096 + idx];
    if (tid < 64) {
        Pb[tid] = pb[stage * 64 + tid];
        Pg[tid] = pg[stage * 64 + tid];
        Pe[tid] = pbe[stage * 64 + tid];
    }
    __syncthreads();

    float acc[2][8][4];
#pragma unroll
    for (int i = 0; i < 2; i++)
#pragma unroll
        for (int j = 0; j < 8; j++)
#pragma unroll
            for (int q = 0; q < 4; q++) acc[i][j][q] = 0.0f;

    mma_block64(acc, Xs + warp * 32 * XS_STRIDE, Ws, g, t);
    ln_gelu_regs(acc, Pb, Pg, Pe, t);

    float* ob = out + (size_t)(blockIdx.x * 256 + warp * 32) * 64;
#pragma unroll
    for (int i = 0; i < 2; i++) {
#pragma unroll
        for (int j = 0; j < 8; j++) {
            int col = j * 8 + t * 2;
            float2 v0 = make_float2(acc[i][j][0], acc[i][j][1]);
            float2 v1 = make_float2(acc[i][j][2], acc[i][j][3]);
            *(float2*)(ob + (i * 16 + g    ) * 64 + col) = v0;
            *(float2*)(ob + (i * 16 + g + 8) * 64 + col) = v1;
        }
    }
}

// ---------------- fused attention apply + 3 exp MLP stages (tensor core) ----
__global__ __launch_bounds__(256) void attn_mlp_tc(
    const float* __restrict__ eW, const float* __restrict__ eb,
    const float* __restrict__ eg, const float* __restrict__ ebe)
{
    extern __shared__ float sm[];
    float* Xs  = sm;
    float* Ws  = sm + 256 * XS_STRIDE;
    float* Pb  = Ws + 64 * WS_STRIDE;
    float* Pg  = Pb + 64;
    float* Pe  = Pg + 64;
    float* Ksm = Pe + 64;

    int tid = threadIdx.x, warp = tid >> 5, lane = tid & 31;
    int g = lane >> 2, t = lane & 3;
    int bh = blockIdx.x >> 4;
    int n0 = (blockIdx.x & 15) << 8;

    const float* qb = g_q + ((size_t)bh * 4096 + n0) * 64;
    for (int idx = tid; idx < 256 * 16; idx += 256) {
        int r = idx >> 4, c4 = (idx & 15) << 2;
        *(float4*)&Xs[r * XS_STRIDE + c4] = *(const float4*)(qb + r * 64 + c4);
    }
    for (int idx = tid; idx < 4096; idx += 256)
        Ws[(idx >> 6) * WS_STRIDE + (idx & 63)] = g_kv[bh * 4096 + idx];
    if (tid < 64) Ksm[tid] = g_ksum[bh * 64 + tid];
    __syncthreads();

    const float* Xw = Xs + warp * 32 * XS_STRIDE;
    float* Xwm = Xs + warp * 32 * XS_STRIDE;

    float acc[2][8][4];
#pragma unroll
    for (int i = 0; i < 2; i++)
#pragma unroll
        for (int j = 0; j < 8; j++)
#pragma unroll
            for (int q = 0; q < 4; q++) acc[i][j][q] = 0.0f;

    // stage 0: y = q @ kv
    mma_block64(acc, Xw, Ws, g, t);

    // per-row inv = 1/(q . ksum + 1e-6)   (4 rows per lane)
    float inv2[2][2];
#pragma unroll
    for (int i = 0; i < 2; i++) {
#pragma unroll
        for (int hlf = 0; hlf < 2; hlf++) {
            const float* xr = Xw + (i * 16 + g + hlf * 8) * XS_STRIDE;
            float dp = 0.0f;
#pragma unroll
            for (int e = 0; e < 16; e++) dp += xr[t + e * 4] * Ksm[t + e * 4];
            dp += __shfl_xor_sync(~0u, dp, 1);
            dp += __shfl_xor_sync(~0u, dp, 2);
            inv2[i][hlf] = 1.0f / (dp + 1e-6f);
        }
    }
    // scale and write back to warp-private rows
#pragma unroll
    for (int i = 0; i < 2; i++) {
#pragma unroll
        for (int j = 0; j < 8; j++) {
            int col = j * 8 + t * 2;
            float2 v0 = make_float2(acc[i][j][0] * inv2[i][0], acc[i][j][1] * inv2[i][0]);
            float2 v1 = make_float2(acc[i][j][2] * inv2[i][1], acc[i][j][3] * inv2[i][1]);
            *(float2*)&Xwm[(i * 16 + g    ) * XS_STRIDE + col] = v0;
            *(float2*)&Xwm[(i * 16 + g + 8) * XS_STRIDE + col] = v1;
        }
    }

    // exp MLP stages s = 2,1,0
    int b = bh / Hh, h = bh - b * Hh;
    float* obase = g_attn + ((size_t)b * 4096 + n0 + warp * 32) * DIMC + h * 64;

    for (int s = 2; s >= 0; s--) {
        __syncthreads();   // all warps done reading Ws from previous stage
        for (int idx = tid; idx < 4096; idx += 256)
            Ws[(idx >> 6) * WS_STRIDE + (idx & 63)] = eW[s * 4096 + idx];
        if (tid < 64) {
            Pb[tid] = eb[s * 64 + tid];
            Pg[tid] = eg[s * 64 + tid];
            Pe[tid] = ebe[s * 64 + tid];
        }
        __syncthreads();

#pragma unroll
        for (int i = 0; i < 2; i++)
#pragma unroll
            for (int j = 0; j < 8; j++)
#pragma unroll
                for (int q = 0; q < 4; q++) acc[i][j][q] = 0.0f;

        mma_block64(acc, Xw, Ws, g, t);
        ln_gelu_regs(acc, Pb, Pg, Pe, t);

        if (s > 0) {
#pragma unroll
            for (int i = 0; i < 2; i++) {
#pragma unroll
                for (int j = 0; j < 8; j++) {
                    int col = j * 8 + t * 2;
                    *(float2*)&Xwm[(i * 16 + g    ) * XS_STRIDE + col] =
                        make_float2(acc[i][j][0], acc[i][j][1]);
                    *(float2*)&Xwm[(i * 16 + g + 8) * XS_STRIDE + col] =
                        make_float2(acc[i][j][2], acc[i][j][3]);
                }
            }
        } else {
#pragma unroll
            for (int i = 0; i < 2; i++) {
#pragma unroll
                for (int j = 0; j < 8; j++) {
                    int col = j * 8 + t * 2;
                    *(float2*)(obase + (size_t)(i * 16 + g    ) * DIMC + col) =
                        make_float2(acc[i][j][0], acc[i][j][1]);
                    *(float2*)(obase + (size_t)(i * 16 + g + 8) * DIMC + col) =
                        make_float2(acc[i][j][2], acc[i][j][3]);
                }
            }
        }
    }
}

// ---------------- vc pooling: mean over 8 consecutive tokens ----------------
__global__ void vpool_kernel()
{
    int idx = blockIdx.x * 256 + threadIdx.x;
    if (idx >= BH * 512 * Dh) return;
    int d   = idx & 63;
    int rest = idx >> 6;
    int n   = rest & 511;
    int bh  = rest >> 9;
    const float* src = g_v + (bh * 4096 + n * 8) * 64 + d;
    float s = 0.0f;
#pragma unroll
    for (int j = 0; j < 8; j++) s += src[j * 64];
    g_vc[idx] = s * 0.125f;
}

// ---------------- kv = (kc/sqrt(512))^T vc, plus k_sum, per (b,h) -----------
__global__ __launch_bounds__(256) void kv_kernel()
{
    int bh = blockIdx.x;
    __shared__ float ks[64][65];
    __shared__ float vs[64][65];
    int tid = threadIdx.x;
    int td = tid & 15, te = tid >> 4;
    float acc[4][4];
#pragma unroll
    for (int i = 0; i < 4; i++)
#pragma unroll
        for (int j = 0; j < 4; j++) acc[i][j] = 0.0f;
    float colsum = 0.0f;
    const float scale = rsqrtf(512.0f);

    for (int nt = 0; nt < 512; nt += 64) {
        for (int i = tid; i < 4096; i += 256) {
            int rr = i >> 6, cc = i & 63;
            ks[rr][cc] = g_kcA[(bh * 512 + nt + rr) * 64 + cc] * scale;
            vs[rr][cc] = g_vc [(bh * 512 + nt + rr) * 64 + cc];
        }
        __syncthreads();
        if (tid < 64) {
            for (int rr = 0; rr < 64; rr++) colsum += ks[rr][tid];
        }
#pragma unroll 4
        for (int nn = 0; nn < 64; nn++) {
            float a[4], bb[4];
#pragma unroll
            for (int i = 0; i < 4; i++) a[i]  = ks[nn][td * 4 + i];
#pragma unroll
            for (int j = 0; j < 4; j++) bb[j] = vs[nn][te * 4 + j];
#pragma unroll
            for (int i = 0; i < 4; i++)
#pragma unroll
                for (int j = 0; j < 4; j++)
                    acc[i][j] = fmaf(a[i], bb[j], acc[i][j]);
        }
        __syncthreads();
    }
#pragma unroll
    for (int i = 0; i < 4; i++)
#pragma unroll
        for (int j = 0; j < 4; j++)
            g_kv[(bh * 64 + td * 4 + i) * 64 + te * 4 + j] = acc[i][j];
    if (tid < 64) g_ksum[bh * 64 + tid] = colsum;
}

// ---------------- launch --------------------------------------------------
extern "C" void kernel_launch(void* const* d_in, const int* in_sizes, int n_in,
                              void* d_out, int out_size)
{
    const float* x   = (const float*)d_in[0];
    const float* Wq  = (const float*)d_in[1];
    const float* Wk  = (const float*)d_in[2];
    const float* Wv  = (const float*)d_in[3];
    const float* pW  = (const float*)d_in[4];
    const float* pb  = (const float*)d_in[5];
    const float* pg  = (const float*)d_in[6];
    const float* pbe = (const float*)d_in[7];
    const float* eW  = (const float*)d_in[8];
    const float* eb  = (const float*)d_in[9];
    const float* eg  = (const float*)d_in[10];
    const float* ebe = (const float*)d_in[11];
    const float* Wo  = (const float*)d_in[12];
    const float* bo  = (const float*)d_in[13];
    float* out = (float*)d_out;

    cudaFuncSetAttribute(qkv_gemm,
        cudaFuncAttributeMaxDynamicSharedMemorySize, GEMM_SMEM_BYTES);
    cudaFuncSetAttribute(out_gemm,
        cudaFuncAttributeMaxDynamicSharedMemorySize, GEMM_SMEM_BYTES);
    cudaFuncSetAttribute(pool_mlp_tc,
        cudaFuncAttributeMaxDynamicSharedMemorySize, MLP_SMEM_BYTES);
    cudaFuncSetAttribute(attn_mlp_tc,
        cudaFuncAttributeMaxDynamicSharedMemorySize, MLP_SMEM_BYTES);

    qkv_gemm<<<dim3(MR / 128, 18), 256, GEMM_SMEM_BYTES>>>(x, Wq, Wk, Wv);
    vpool_kernel<<<(BH * 512 * Dh + 255) / 256, 256>>>();
    pool_mlp_tc<<<BH * 2048 / 256, 256, MLP_SMEM_BYTES>>>(0, pW, pb, pg, pbe);
    pool_mlp_tc<<<BH * 1024 / 256, 256, MLP_SMEM_BYTES>>>(1, pW, pb, pg, pbe);
    pool_mlp_tc<<<BH * 512 / 256, 256, MLP_SMEM_BYTES>>>(2, pW, pb, pg, pbe);
    kv_kernel<<<BH, 256>>>();
    attn_mlp_tc<<<BH * 16, 256, MLP_SMEM_BYTES>>>(eW, eb, eg, ebe);
    out_gemm<<<dim3(MR / 128, 6), 256, GEMM_SMEM_BYTES>>>(Wo, bo, out);
}

// round 6
// speedup vs baseline: 2.8543x; 1.1136x over previous
#include <cuda_runtime.h>
#include <math.h>
#include <stdint.h>

#define Bz   8
#define Nseq 4096
#define DIMC 768
#define Hh   12
#define Dh   64
#define BH   (Bz*Hh)        // 96
#define MR   (Bz*Nseq)      // 32768

// ---------------- scratch (device globals; no allocations allowed) ----------
__device__ float g_q[BH*Nseq*Dh];
__device__ float g_k[BH*Nseq*Dh];
__device__ float g_v[BH*Nseq*Dh];
__device__ float g_kcA[BH*2048*Dh];
__device__ float g_kcB[BH*1024*Dh];
__device__ float g_vc[BH*512*Dh];
__device__ float g_kv[BH*Dh*Dh];
__device__ float g_ksum[BH*Dh];
__device__ float g_attn[MR*DIMC];

__device__ __forceinline__ float gelu_f(float t) {
    return 0.5f * t * (1.0f + erff(t * 0.70710678118654752f));
}
__device__ __forceinline__ float fmap_f(float t) {   // elu(t)+1
    return t > 0.0f ? t + 1.0f : expf(t);
}
__device__ __forceinline__ uint32_t f2tf32(float f) {
    uint32_t r;
    asm("cvt.rna.tf32.f32 %0, %1;" : "=r"(r) : "f"(f));
    return r;
}
__device__ __forceinline__ void split_tf32(float x, uint32_t& hi, uint32_t& lo) {
    hi = f2tf32(x);
    lo = f2tf32(x - __uint_as_float(hi));
}
__device__ __forceinline__ void mma_tf32(float c[4],
    uint32_t a0, uint32_t a1, uint32_t a2, uint32_t a3,
    uint32_t b0, uint32_t b1)
{
    asm volatile(
        "mma.sync.aligned.m16n8k8.row.col.f32.tf32.tf32.f32 "
        "{%0,%1,%2,%3}, {%4,%5,%6,%7}, {%8,%9}, {%0,%1,%2,%3};"
        : "+f"(c[0]), "+f"(c[1]), "+f"(c[2]), "+f"(c[3])
        : "r"(a0), "r"(a1), "r"(a2), "r"(a3), "r"(b0), "r"(b1));
}
__device__ __forceinline__ void cp_async16(uint32_t dst, const void* src) {
    asm volatile("cp.async.cg.shared.global [%0], [%1], 16;" :: "r"(dst), "l"(src));
}

// =======================================================================
// Big GEMMs (unchanged): tf32, cp.async double-buffered.
// =======================================================================
#define AS_STRIDE 36
#define BS_STRIDE 136
#define AS_TILE   (128 * AS_STRIDE)
#define BS_TILE   (32 * BS_STRIDE)
#define NT        (DIMC / 32)
#define GEMM_SMEM_BYTES ((2 * AS_TILE + 2 * BS_TILE) * 4)

#define GEMM_PROLOG \
    extern __shared__ float smemg[]; \
    float* Asf = smemg; \
    float* Bsf = smemg + 2 * AS_TILE; \
    uint32_t As_base = (uint32_t)__cvta_generic_to_shared(Asf); \
    uint32_t Bs_base = (uint32_t)__cvta_generic_to_shared(Bsf); \
    int tid = threadIdx.x; \
    int warp = tid >> 5, lane = tid & 31; \
    int g = lane >> 2, t = lane & 3; \
    int wm = warp >> 1, wn = warp & 1; \
    int a_row = tid >> 1, a_col = (tid & 1) << 4; \
    int b_row = tid >> 3, b_col = (tid & 7) << 4; \
    float acc[2][8][4]; \
    _Pragma("unroll") \
    for (int i = 0; i < 2; i++) \
        _Pragma("unroll") \
        for (int j = 0; j < 8; j++) \
            _Pragma("unroll") \
            for (int q = 0; q < 4; q++) acc[i][j][q] = 0.0f;

#define GEMM_CPLOAD(APTR_BASE, K0, BUF) { \
    const float* ap_ = (APTR_BASE) + (K0) + a_col; \
    const float* bp_ = W + (size_t)((K0) + b_row) * DIMC + n0 + b_col; \
    uint32_t asd = As_base + (uint32_t)(((BUF) * AS_TILE + a_row * AS_STRIDE + a_col) * 4); \
    uint32_t bsd = Bs_base + (uint32_t)(((BUF) * BS_TILE + b_row * BS_STRIDE + b_col) * 4); \
    _Pragma("unroll") \
    for (int u = 0; u < 4; u++) { \
        cp_async16(asd + u * 16, ap_ + u * 4); \
        cp_async16(bsd + u * 16, bp_ + u * 4); \
    } }

#define GEMM_COMPUTE(BUF) { \
    const float* Asc = Asf + (BUF) * AS_TILE; \
    const float* Bsc = Bsf + (BUF) * BS_TILE; \
    _Pragma("unroll") \
    for (int kk = 0; kk < 4; kk++) { \
        int ks = kk * 8; \
        uint32_t af[2][4]; \
        _Pragma("unroll") \
        for (int i = 0; i < 2; i++) { \
            int rb = wm * 32 + i * 16; \
            af[i][0] = f2tf32(Asc[(rb + g    ) * AS_STRIDE + ks + t    ]); \
            af[i][1] = f2tf32(Asc[(rb + g + 8) * AS_STRIDE + ks + t    ]); \
            af[i][2] = f2tf32(Asc[(rb + g    ) * AS_STRIDE + ks + t + 4]); \
            af[i][3] = f2tf32(Asc[(rb + g + 8) * AS_STRIDE + ks + t + 4]); \
        } \
        uint32_t bf[8][2]; \
        _Pragma("unroll") \
        for (int j = 0; j < 8; j++) { \
            int cb = wn * 64 + j * 8 + g; \
            bf[j][0] = f2tf32(Bsc[(ks + t    ) * BS_STRIDE + cb]); \
            bf[j][1] = f2tf32(Bsc[(ks + t + 4) * BS_STRIDE + cb]); \
        } \
        _Pragma("unroll") \
        for (int i = 0; i < 2; i++) \
            _Pragma("unroll") \
            for (int j = 0; j < 8; j++) \
                mma_tf32(acc[i][j], af[i][0], af[i][1], af[i][2], af[i][3], \
                         bf[j][0], bf[j][1]); \
    } }

#define GEMM_MAINLOOP(APTR_BASE) \
    GEMM_CPLOAD(APTR_BASE, 0, 0) \
    asm volatile("cp.async.commit_group;"); \
    _Pragma("unroll 1") \
    for (int kt = 0; kt < NT; kt++) { \
        if (kt + 1 < NT) { \
            GEMM_CPLOAD(APTR_BASE, (kt + 1) * 32, (kt + 1) & 1) \
            asm volatile("cp.async.commit_group;"); \
            asm volatile("cp.async.wait_group 1;"); \
        } else { \
            asm volatile("cp.async.wait_group 0;"); \
        } \
        __syncthreads(); \
        GEMM_COMPUTE(kt & 1) \
        __syncthreads(); \
    }

__global__ __launch_bounds__(256, 2) void qkv_gemm(
    const float* __restrict__ X, const float* __restrict__ Wq,
    const float* __restrict__ Wk, const float* __restrict__ Wv)
{
    GEMM_PROLOG
    int nb   = blockIdx.y;
    int wsel = nb / 6;
    const float* W = (wsel == 0) ? Wq : (wsel == 1 ? Wk : Wv);
    float*       O = (wsel == 0) ? g_q : (wsel == 1 ? g_k : g_v);
    int n0 = (nb % 6) * 128;
    int m0 = blockIdx.x * 128;
    const float* Abase = X + (size_t)(m0 + a_row) * DIMC;

    GEMM_MAINLOOP(Abase)

#pragma unroll
    for (int i = 0; i < 2; i++) {
#pragma unroll
        for (int j = 0; j < 8; j++) {
            int r0 = m0 + wm * 32 + i * 16 + g;
            int c  = n0 + wn * 64 + j * 8 + t * 2;
            int h = c >> 6, d = c & 63;
#pragma unroll
            for (int half = 0; half < 2; half++) {
                int m = half ? r0 + 8 : r0;
                int b = m >> 12, n = m & 4095;
                float v0 = acc[i][j][half * 2 + 0];
                float v1 = acc[i][j][half * 2 + 1];
                if (wsel < 2) { v0 = fmap_f(v0); v1 = fmap_f(v1); }
                float* dst = O + (((size_t)(b * Hh + h) * Nseq + n) * Dh + d);
                dst[0] = v0; dst[1] = v1;
            }
        }
    }
}

__global__ __launch_bounds__(256, 2) void out_gemm(
    const float* __restrict__ W, const float* __restrict__ bias,
    float* __restrict__ out)
{
    GEMM_PROLOG
    int n0 = blockIdx.y * 128;
    int m0 = blockIdx.x * 128;
    const float* Abase = g_attn + (size_t)(m0 + a_row) * DIMC;

    GEMM_MAINLOOP(Abase)

#pragma unroll
    for (int i = 0; i < 2; i++) {
#pragma unroll
        for (int j = 0; j < 8; j++) {
            int r0 = m0 + wm * 32 + i * 16 + g;
            int c  = n0 + wn * 64 + j * 8 + t * 2;
            float b0 = bias[c], b1 = bias[c + 1];
            out[(size_t)r0 * DIMC + c]           = acc[i][j][0] + b0;
            out[(size_t)r0 * DIMC + c + 1]       = acc[i][j][1] + b1;
            out[(size_t)(r0 + 8) * DIMC + c]     = acc[i][j][2] + b0;
            out[(size_t)(r0 + 8) * DIMC + c + 1] = acc[i][j][3] + b1;
        }
    }
}

// =======================================================================
// Tensor-core 64-wide MLP machinery (split-tf32, ~fp32 accuracy).
// Block = 256 rows x 64 cols, K=64. 8 warps, each owns 32 rows.
// Weights PRE-SPLIT into Whi/Wlo smem (tf32 bit patterns) — inner loop
// is pure LDS + MMA on the B side. 2 CTAs/SM via launch_bounds(256,2).
// =======================================================================
#define XS_STRIDE 68
#define WS_STRIDE 72
#define MLP_SMEM_FLOATS (256 * XS_STRIDE + 2 * 64 * WS_STRIDE + 4 * 64)
#define MLP_SMEM_BYTES  (MLP_SMEM_FLOATS * 4)

// split w into Whi/Wlo smem (tf32 bits), one pass over 4096 elements
__device__ __forceinline__ void load_split_weights(
    uint32_t* Whi, uint32_t* Wlo, const float* __restrict__ src, int tid)
{
    for (int idx = tid; idx < 4096; idx += 256) {
        float w = src[idx];
        uint32_t hi, lo;
        split_tf32(w, hi, lo);
        int off = (idx >> 6) * WS_STRIDE + (idx & 63);
        Whi[off] = hi;
        Wlo[off] = lo;
    }
}

__device__ __forceinline__ void mma_block64(
    float acc[2][8][4], const float* Xw,
    const uint32_t* Whi, const uint32_t* Wlo, int g, int t)
{
#pragma unroll
    for (int ks8 = 0; ks8 < 8; ks8++) {
        int ks = ks8 * 8;
        uint32_t aHi[2][4], aLo[2][4];
#pragma unroll
        for (int i = 0; i < 2; i++) {
            const float* xr = Xw + (i * 16 + g) * XS_STRIDE + ks;
            split_tf32(xr[t],                     aHi[i][0], aLo[i][0]);
            split_tf32(xr[8 * XS_STRIDE + t],     aHi[i][1], aLo[i][1]);
            split_tf32(xr[t + 4],                 aHi[i][2], aLo[i][2]);
            split_tf32(xr[8 * XS_STRIDE + t + 4], aHi[i][3], aLo[i][3]);
        }
#pragma unroll
        for (int j = 0; j < 8; j++) {
            int cb = j * 8 + g;
            uint32_t bh0 = Whi[(ks + t    ) * WS_STRIDE + cb];
            uint32_t bh1 = Whi[(ks + t + 4) * WS_STRIDE + cb];
            uint32_t bl0 = Wlo[(ks + t    ) * WS_STRIDE + cb];
            uint32_t bl1 = Wlo[(ks + t + 4) * WS_STRIDE + cb];
#pragma unroll
            for (int i = 0; i < 2; i++) {
                mma_tf32(acc[i][j], aHi[i][0], aHi[i][1], aHi[i][2], aHi[i][3], bh0, bh1);
                mma_tf32(acc[i][j], aLo[i][0], aLo[i][1], aLo[i][2], aLo[i][3], bh0, bh1);
                mma_tf32(acc[i][j], aHi[i][0], aHi[i][1], aHi[i][2], aHi[i][3], bl0, bl1);
            }
        }
    }
}

// bias + LN + gelu entirely in registers (quad shuffles for row stats)
__device__ __forceinline__ void ln_gelu_regs(
    float acc[2][8][4], const float* Pb, const float* Pg, const float* Pe, int t)
{
#pragma unroll
    for (int i = 0; i < 2; i++) {
        float s1A = 0, s2A = 0, s1B = 0, s2B = 0;
#pragma unroll
        for (int j = 0; j < 8; j++) {
#pragma unroll
            for (int q = 0; q < 4; q++) {
                int col = j * 8 + t * 2 + (q & 1);
                float v = acc[i][j][q] + Pb[col];
                acc[i][j][q] = v;
                if (q < 2) { s1A += v; s2A += v * v; }
                else       { s1B += v; s2B += v * v; }
            }
        }
        s1A += __shfl_xor_sync(~0u, s1A, 1); s2A += __shfl_xor_sync(~0u, s2A, 1);
        s1B += __shfl_xor_sync(~0u, s1B, 1); s2B += __shfl_xor_sync(~0u, s2B, 1);
        s1A += __shfl_xor_sync(~0u, s1A, 2); s2A += __shfl_xor_sync(~0u, s2A, 2);
        s1B += __shfl_xor_sync(~0u, s1B, 2); s2B += __shfl_xor_sync(~0u, s2B, 2);
        float muA = s1A * (1.0f / 64.0f);
        float muB = s1B * (1.0f / 64.0f);
        float rA = rsqrtf(s2A * (1.0f / 64.0f) - muA * muA + 1e-5f);
        float rB = rsqrtf(s2B * (1.0f / 64.0f) - muB * muB + 1e-5f);
#pragma unroll
        for (int j = 0; j < 8; j++) {
#pragma unroll
            for (int q = 0; q < 4; q++) {
                int col = j * 8 + t * 2 + (q & 1);
                float mu = (q < 2) ? muA : muB;
                float rv = (q < 2) ? rA : rB;
                acc[i][j][q] = gelu_f((acc[i][j][q] - mu) * rv * Pg[col] + Pe[col]);
            }
        }
    }
}

// ---------------- pool stage (tensor core): pair-mean + MLP(LN+gelu) --------
__global__ __launch_bounds__(256, 2) void pool_mlp_tc(
    int stage,
    const float* __restrict__ pW, const float* __restrict__ pb,
    const float* __restrict__ pg, const float* __restrict__ pbe)
{
    extern __shared__ float sm[];
    float*    Xs  = sm;
    uint32_t* Whi = (uint32_t*)(sm + 256 * XS_STRIDE);
    uint32_t* Wlo = Whi + 64 * WS_STRIDE;
    float*    Pb  = (float*)(Wlo + 64 * WS_STRIDE);
    float*    Pg  = Pb + 64;
    float*    Pe  = Pg + 64;

    const float* in; float* out; int s_in, s_out;
    if (stage == 0)      { in = g_k;   out = g_kcA; s_in = 4096; s_out = 2048; }
    else if (stage == 1) { in = g_kcA; out = g_kcB; s_in = 2048; s_out = 1024; }
    else                 { in = g_kcB; out = g_kcA; s_in = 1024; s_out = 512;  }

    int tid = threadIdx.x, warp = tid >> 5, lane = tid & 31;
    int g = lane >> 2, t = lane & 3;

    // pooled activation load: X row = mean of input rows 2n, 2n+1
    for (int idx = tid; idx < 256 * 16; idx += 256) {
        int r = idx >> 4, c4 = (idx & 15) << 2;
        int rg = blockIdx.x * 256 + r;
        int bh = rg / s_out, n = rg - bh * s_out;
        const float* src = in + ((size_t)bh * s_in + 2 * n) * 64 + c4;
        float4 a = *(const float4*)src;
        float4 b = *(const float4*)(src + 64);
        float4 v;
        v.x = 0.5f * (a.x + b.x); v.y = 0.5f * (a.y + b.y);
        v.z = 0.5f * (a.z + b.z); v.w = 0.5f * (a.w + b.w);
        *(float4*)&Xs[r * XS_STRIDE + c4] = v;
    }
    load_split_weights(Whi, Wlo, pW + stage * 4096, tid);
    if (tid < 64) {
        Pb[tid] = pb[stage * 64 + tid];
        Pg[tid] = pg[stage * 64 + tid];
        Pe[tid] = pbe[stage * 64 + tid];
    }
    __syncthreads();

    float acc[2][8][4];
#pragma unroll
    for (int i = 0; i < 2; i++)
#pragma unroll
        for (int j = 0; j < 8; j++)
#pragma unroll
            for (int q = 0; q < 4; q++) acc[i][j][q] = 0.0f;

    mma_block64(acc, Xs + warp * 32 * XS_STRIDE, Whi, Wlo, g, t);
    ln_gelu_regs(acc, Pb, Pg, Pe, t);

    float* ob = out + (size_t)(blockIdx.x * 256 + warp * 32) * 64;
#pragma unroll
    for (int i = 0; i < 2; i++) {
#pragma unroll
        for (int j = 0; j < 8; j++) {
            int col = j * 8 + t * 2;
            float2 v0 = make_float2(acc[i][j][0], acc[i][j][1]);
            float2 v1 = make_float2(acc[i][j][2], acc[i][j][3]);
            *(float2*)(ob + (i * 16 + g    ) * 64 + col) = v0;
            *(float2*)(ob + (i * 16 + g + 8) * 64 + col) = v1;
        }
    }
}

// ---------------- fused attention apply + 3 exp MLP stages (tensor core) ----
__global__ __launch_bounds__(256, 2) void attn_mlp_tc(
    const float* __restrict__ eW, const float* __restrict__ eb,
    const float* __restrict__ eg, const float* __restrict__ ebe)
{
    extern __shared__ float sm[];
    float*    Xs  = sm;
    uint32_t* Whi = (uint32_t*)(sm + 256 * XS_STRIDE);
    uint32_t* Wlo = Whi + 64 * WS_STRIDE;
    float*    Pb  = (float*)(Wlo + 64 * WS_STRIDE);
    float*    Pg  = Pb + 64;
    float*    Pe  = Pg + 64;
    float*    Ksm = Pe + 64;

    int tid = threadIdx.x, warp = tid >> 5, lane = tid & 31;
    int g = lane >> 2, t = lane & 3;
    int bh = blockIdx.x >> 4;
    int n0 = (blockIdx.x & 15) << 8;

    const float* qb = g_q + ((size_t)bh * 4096 + n0) * 64;
    for (int idx = tid; idx < 256 * 16; idx += 256) {
        int r = idx >> 4, c4 = (idx & 15) << 2;
        *(float4*)&Xs[r * XS_STRIDE + c4] = *(const float4*)(qb + r * 64 + c4);
    }
    load_split_weights(Whi, Wlo, g_kv + bh * 4096, tid);
    if (tid < 64) Ksm[tid] = g_ksum[bh * 64 + tid];
    __syncthreads();

    const float* Xw  = Xs + warp * 32 * XS_STRIDE;
    float*       Xwm = Xs + warp * 32 * XS_STRIDE;

    float acc[2][8][4];
#pragma unroll
    for (int i = 0; i < 2; i++)
#pragma unroll
        for (int j = 0; j < 8; j++)
#pragma unroll
            for (int q = 0; q < 4; q++) acc[i][j][q] = 0.0f;

    // stage 0: y = q @ kv
    mma_block64(acc, Xw, Whi, Wlo, g, t);

    // per-row inv = 1/(q . ksum + 1e-6)   (4 rows per lane)
    float inv2[2][2];
#pragma unroll
    for (int i = 0; i < 2; i++) {
#pragma unroll
        for (int hlf = 0; hlf < 2; hlf++) {
            const float* xr = Xw + (i * 16 + g + hlf * 8) * XS_STRIDE;
            float dp = 0.0f;
#pragma unroll
            for (int e = 0; e < 16; e++) dp += xr[t + e * 4] * Ksm[t + e * 4];
            dp += __shfl_xor_sync(~0u, dp, 1);
            dp += __shfl_xor_sync(~0u, dp, 2);
            inv2[i][hlf] = 1.0f / (dp + 1e-6f);
        }
    }
    // scale and write back to warp-private rows
#pragma unroll
    for (int i = 0; i < 2; i++) {
#pragma unroll
        for (int j = 0; j < 8; j++) {
            int col = j * 8 + t * 2;
            float2 v0 = make_float2(acc[i][j][0] * inv2[i][0], acc[i][j][1] * inv2[i][0]);
            float2 v1 = make_float2(acc[i][j][2] * inv2[i][1], acc[i][j][3] * inv2[i][1]);
            *(float2*)&Xwm[(i * 16 + g    ) * XS_STRIDE + col] = v0;
            *(float2*)&Xwm[(i * 16 + g + 8) * XS_STRIDE + col] = v1;
        }
    }

    // exp MLP stages s = 2,1,0
    int b = bh / Hh, h = bh - b * Hh;
    float* obase = g_attn + ((size_t)b * 4096 + n0 + warp * 32) * DIMC + h * 64;

    for (int s = 2; s >= 0; s--) {
        __syncthreads();   // all warps done reading W from previous stage
        load_split_weights(Whi, Wlo, eW + s * 4096, tid);
        if (tid < 64) {
            Pb[tid] = eb[s * 64 + tid];
            Pg[tid] = eg[s * 64 + tid];
            Pe[tid] = ebe[s * 64 + tid];
        }
        __syncthreads();

#pragma unroll
        for (int i = 0; i < 2; i++)
#pragma unroll
            for (int j = 0; j < 8; j++)
#pragma unroll
                for (int q = 0; q < 4; q++) acc[i][j][q] = 0.0f;

        mma_block64(acc, Xw, Whi, Wlo, g, t);
        ln_gelu_regs(acc, Pb, Pg, Pe, t);

        if (s > 0) {
#pragma unroll
            for (int i = 0; i < 2; i++) {
#pragma unroll
                for (int j = 0; j < 8; j++) {
                    int col = j * 8 + t * 2;
                    *(float2*)&Xwm[(i * 16 + g    ) * XS_STRIDE + col] =
                        make_float2(acc[i][j][0], acc[i][j][1]);
                    *(float2*)&Xwm[(i * 16 + g + 8) * XS_STRIDE + col] =
                        make_float2(acc[i][j][2], acc[i][j][3]);
                }
            }
        } else {
#pragma unroll
            for (int i = 0; i < 2; i++) {
#pragma unroll
                for (int j = 0; j < 8; j++) {
                    int col = j * 8 + t * 2;
                    *(float2*)(obase + (size_t)(i * 16 + g    ) * DIMC + col) =
                        make_float2(acc[i][j][0], acc[i][j][1]);
                    *(float2*)(obase + (size_t)(i * 16 + g + 8) * DIMC + col) =
                        make_float2(acc[i][j][2], acc[i][j][3]);
                }
            }
        }
    }
}

// ---------------- vc pooling: mean over 8 consecutive tokens ----------------
__global__ void vpool_kernel()
{
    int idx = blockIdx.x * 256 + threadIdx.x;
    if (idx >= BH * 512 * Dh) return;
    int d   = idx & 63;
    int rest = idx >> 6;
    int n   = rest & 511;
    int bh  = rest >> 9;
    const float* src = g_v + (bh * 4096 + n * 8) * 64 + d;
    float s = 0.0f;
#pragma unroll
    for (int j = 0; j < 8; j++) s += src[j * 64];
    g_vc[idx] = s * 0.125f;
}

// ---------------- kv = (kc/sqrt(512))^T vc, plus k_sum, per (b,h) -----------
__global__ __launch_bounds__(256) void kv_kernel()
{
    int bh = blockIdx.x;
    __shared__ float ks[64][65];
    __shared__ float vs[64][65];
    int tid = threadIdx.x;
    int td = tid & 15, te = tid >> 4;
    float acc[4][4];
#pragma unroll
    for (int i = 0; i < 4; i++)
#pragma unroll
        for (int j = 0; j < 4; j++) acc[i][j] = 0.0f;
    float colsum = 0.0f;
    const float scale = rsqrtf(512.0f);

    for (int nt = 0; nt < 512; nt += 64) {
        for (int i = tid; i < 4096; i += 256) {
            int rr = i >> 6, cc = i & 63;
            ks[rr][cc] = g_kcA[(bh * 512 + nt + rr) * 64 + cc] * scale;
            vs[rr][cc] = g_vc [(bh * 512 + nt + rr) * 64 + cc];
        }
        __syncthreads();
        if (tid < 64) {
            for (int rr = 0; rr < 64; rr++) colsum += ks[rr][tid];
        }
#pragma unroll 4
        for (int nn = 0; nn < 64; nn++) {
            float a[4], bb[4];
#pragma unroll
            for (int i = 0; i < 4; i++) a[i]  = ks[nn][td * 4 + i];
#pragma unroll
            for (int j = 0; j < 4; j++) bb[j] = vs[nn][te * 4 + j];
#pragma unroll
            for (int i = 0; i < 4; i++)
#pragma unroll
                for (int j = 0; j < 4; j++)
                    acc[i][j] = fmaf(a[i], bb[j], acc[i][j]);
        }
        __syncthreads();
    }
#pragma unroll
    for (int i = 0; i < 4; i++)
#pragma unroll
        for (int j = 0; j < 4; j++)
            g_kv[(bh * 64 + td * 4 + i) * 64 + te * 4 + j] = acc[i][j];
    if (tid < 64) g_ksum[bh * 64 + tid] = colsum;
}

// ---------------- launch --------------------------------------------------
extern "C" void kernel_launch(void* const* d_in, const int* in_sizes, int n_in,
                              void* d_out, int out_size)
{
    const float* x   = (const float*)d_in[0];
    const float* Wq  = (const float*)d_in[1];
    const float* Wk  = (const float*)d_in[2];
    const float* Wv  = (const float*)d_in[3];
    const float* pW  = (const float*)d_in[4];
    const float* pb  = (const float*)d_in[5];
    const float* pg  = (const float*)d_in[6];
    const float* pbe = (const float*)d_in[7];
    const float* eW  = (const float*)d_in[8];
    const float* eb  = (const float*)d_in[9];
    const float* eg  = (const float*)d_in[10];
    const float* ebe = (const float*)d_in[11];
    const float* Wo  = (const float*)d_in[12];
    const float* bo  = (const float*)d_in[13];
    float* out = (float*)d_out;

    cudaFuncSetAttribute(qkv_gemm,
        cudaFuncAttributeMaxDynamicSharedMemorySize, GEMM_SMEM_BYTES);
    cudaFuncSetAttribute(out_gemm,
        cudaFuncAttributeMaxDynamicSharedMemorySize, GEMM_SMEM_BYTES);
    cudaFuncSetAttribute(pool_mlp_tc,
        cudaFuncAttributeMaxDynamicSharedMemorySize, MLP_SMEM_BYTES);
    cudaFuncSetAttribute(attn_mlp_tc,
        cudaFuncAttributeMaxDynamicSharedMemorySize, MLP_SMEM_BYTES);

    qkv_gemm<<<dim3(MR / 128, 18), 256, GEMM_SMEM_BYTES>>>(x, Wq, Wk, Wv);
    vpool_kernel<<<(BH * 512 * Dh + 255) / 256, 256>>>();
    pool_mlp_tc<<<BH * 2048 / 256, 256, MLP_SMEM_BYTES>>>(0, pW, pb, pg, pbe);
    pool_mlp_tc<<<BH * 1024 / 256, 256, MLP_SMEM_BYTES>>>(1, pW, pb, pg, pbe);
    pool_mlp_tc<<<BH * 512 / 256, 256, MLP_SMEM_BYTES>>>(2, pW, pb, pg, pbe);
    kv_kernel<<<BH, 256>>>();
    attn_mlp_tc<<<BH * 16, 256, MLP_SMEM_BYTES>>>(eW, eb, eg, ebe);
    out_gemm<<<dim3(MR / 128, 6), 256, GEMM_SMEM_BYTES>>>(Wo, bo, out);
}

// round 7
// speedup vs baseline: 3.0410x; 1.0654x over previous
#include <cuda_runtime.h>
#include <math.h>
#include <stdint.h>

#define Bz   8
#define Nseq 4096
#define DIMC 768
#define Hh   12
#define Dh   64
#define BH   (Bz*Hh)        // 96
#define MR   (Bz*Nseq)      // 32768

// ---------------- scratch (device globals; no allocations allowed) ----------
__device__ float g_q[BH*Nseq*Dh];
__device__ float g_k[BH*Nseq*Dh];
__device__ float g_v[BH*Nseq*Dh];
__device__ float g_kcA[BH*2048*Dh];
__device__ float g_kcB[BH*1024*Dh];
__device__ float g_vc[BH*512*Dh];
__device__ float g_kv[BH*Dh*Dh];
__device__ float g_ksum[BH*Dh];
__device__ float g_attn[MR*DIMC];

__device__ __forceinline__ float gelu_f(float t) {
    return 0.5f * t * (1.0f + erff(t * 0.70710678118654752f));
}
__device__ __forceinline__ float fmap_f(float t) {   // elu(t)+1
    return t > 0.0f ? t + 1.0f : expf(t);
}
__device__ __forceinline__ uint32_t f2tf32(float f) {
    uint32_t r;
    asm("cvt.rna.tf32.f32 %0, %1;" : "=r"(r) : "f"(f));
    return r;
}
__device__ __forceinline__ void mma_tf32(float c[4],
    uint32_t a0, uint32_t a1, uint32_t a2, uint32_t a3,
    uint32_t b0, uint32_t b1)
{
    asm volatile(
        "mma.sync.aligned.m16n8k8.row.col.f32.tf32.tf32.f32 "
        "{%0,%1,%2,%3}, {%4,%5,%6,%7}, {%8,%9}, {%0,%1,%2,%3};"
        : "+f"(c[0]), "+f"(c[1]), "+f"(c[2]), "+f"(c[3])
        : "r"(a0), "r"(a1), "r"(a2), "r"(a3), "r"(b0), "r"(b1));
}
__device__ __forceinline__ void cp_async16(uint32_t dst, const void* src) {
    asm volatile("cp.async.cg.shared.global [%0], [%1], 16;" :: "r"(dst), "l"(src));
}

// =======================================================================
// Big GEMMs (unchanged): tf32, cp.async double-buffered.
// =======================================================================
#define AS_STRIDE 36
#define BS_STRIDE 136
#define AS_TILE   (128 * AS_STRIDE)
#define BS_TILE   (32 * BS_STRIDE)
#define NT        (DIMC / 32)
#define GEMM_SMEM_BYTES ((2 * AS_TILE + 2 * BS_TILE) * 4)

#define GEMM_PROLOG \
    extern __shared__ float smemg[]; \
    float* Asf = smemg; \
    float* Bsf = smemg + 2 * AS_TILE; \
    uint32_t As_base = (uint32_t)__cvta_generic_to_shared(Asf); \
    uint32_t Bs_base = (uint32_t)__cvta_generic_to_shared(Bsf); \
    int tid = threadIdx.x; \
    int warp = tid >> 5, lane = tid & 31; \
    int g = lane >> 2, t = lane & 3; \
    int wm = warp >> 1, wn = warp & 1; \
    int a_row = tid >> 1, a_col = (tid & 1) << 4; \
    int b_row = tid >> 3, b_col = (tid & 7) << 4; \
    float acc[2][8][4]; \
    _Pragma("unroll") \
    for (int i = 0; i < 2; i++) \
        _Pragma("unroll") \
        for (int j = 0; j < 8; j++) \
            _Pragma("unroll") \
            for (int q = 0; q < 4; q++) acc[i][j][q] = 0.0f;

#define GEMM_CPLOAD(APTR_BASE, K0, BUF) { \
    const float* ap_ = (APTR_BASE) + (K0) + a_col; \
    const float* bp_ = W + (size_t)((K0) + b_row) * DIMC + n0 + b_col; \
    uint32_t asd = As_base + (uint32_t)(((BUF) * AS_TILE + a_row * AS_STRIDE + a_col) * 4); \
    uint32_t bsd = Bs_base + (uint32_t)(((BUF) * BS_TILE + b_row * BS_STRIDE + b_col) * 4); \
    _Pragma("unroll") \
    for (int u = 0; u < 4; u++) { \
        cp_async16(asd + u * 16, ap_ + u * 4); \
        cp_async16(bsd + u * 16, bp_ + u * 4); \
    } }

#define GEMM_COMPUTE(BUF) { \
    const float* Asc = Asf + (BUF) * AS_TILE; \
    const float* Bsc = Bsf + (BUF) * BS_TILE; \
    _Pragma("unroll") \
    for (int kk = 0; kk < 4; kk++) { \
        int ks = kk * 8; \
        uint32_t af[2][4]; \
        _Pragma("unroll") \
        for (int i = 0; i < 2; i++) { \
            int rb = wm * 32 + i * 16; \
            af[i][0] = f2tf32(Asc[(rb + g    ) * AS_STRIDE + ks + t    ]); \
            af[i][1] = f2tf32(Asc[(rb + g + 8) * AS_STRIDE + ks + t    ]); \
            af[i][2] = f2tf32(Asc[(rb + g    ) * AS_STRIDE + ks + t + 4]); \
            af[i][3] = f2tf32(Asc[(rb + g + 8) * AS_STRIDE + ks + t + 4]); \
        } \
        uint32_t bf[8][2]; \
        _Pragma("unroll") \
        for (int j = 0; j < 8; j++) { \
            int cb = wn * 64 + j * 8 + g; \
            bf[j][0] = f2tf32(Bsc[(ks + t    ) * BS_STRIDE + cb]); \
            bf[j][1] = f2tf32(Bsc[(ks + t + 4) * BS_STRIDE + cb]); \
        } \
        _Pragma("unroll") \
        for (int i = 0; i < 2; i++) \
            _Pragma("unroll") \
            for (int j = 0; j < 8; j++) \
                mma_tf32(acc[i][j], af[i][0], af[i][1], af[i][2], af[i][3], \
                         bf[j][0], bf[j][1]); \
    } }

#define GEMM_MAINLOOP(APTR_BASE) \
    GEMM_CPLOAD(APTR_BASE, 0, 0) \
    asm volatile("cp.async.commit_group;"); \
    _Pragma("unroll 1") \
    for (int kt = 0; kt < NT; kt++) { \
        if (kt + 1 < NT) { \
            GEMM_CPLOAD(APTR_BASE, (kt + 1) * 32, (kt + 1) & 1) \
            asm volatile("cp.async.commit_group;"); \
            asm volatile("cp.async.wait_group 1;"); \
        } else { \
            asm volatile("cp.async.wait_group 0;"); \
        } \
        __syncthreads(); \
        GEMM_COMPUTE(kt & 1) \
        __syncthreads(); \
    }

__global__ __launch_bounds__(256, 2) void qkv_gemm(
    const float* __restrict__ X, const float* __restrict__ Wq,
    const float* __restrict__ Wk, const float* __restrict__ Wv)
{
    GEMM_PROLOG
    int nb   = blockIdx.y;
    int wsel = nb / 6;
    const float* W = (wsel == 0) ? Wq : (wsel == 1 ? Wk : Wv);
    float*       O = (wsel == 0) ? g_q : (wsel == 1 ? g_k : g_v);
    int n0 = (nb % 6) * 128;
    int m0 = blockIdx.x * 128;
    const float* Abase = X + (size_t)(m0 + a_row) * DIMC;

    GEMM_MAINLOOP(Abase)

#pragma unroll
    for (int i = 0; i < 2; i++) {
#pragma unroll
        for (int j = 0; j < 8; j++) {
            int r0 = m0 + wm * 32 + i * 16 + g;
            int c  = n0 + wn * 64 + j * 8 + t * 2;
            int h = c >> 6, d = c & 63;
#pragma unroll
            for (int half = 0; half < 2; half++) {
                int m = half ? r0 + 8 : r0;
                int b = m >> 12, n = m & 4095;
                float v0 = acc[i][j][half * 2 + 0];
                float v1 = acc[i][j][half * 2 + 1];
                if (wsel < 2) { v0 = fmap_f(v0); v1 = fmap_f(v1); }
                float* dst = O + (((size_t)(b * Hh + h) * Nseq + n) * Dh + d);
                dst[0] = v0; dst[1] = v1;
            }
        }
    }
}

__global__ __launch_bounds__(256, 2) void out_gemm(
    const float* __restrict__ W, const float* __restrict__ bias,
    float* __restrict__ out)
{
    GEMM_PROLOG
    int n0 = blockIdx.y * 128;
    int m0 = blockIdx.x * 128;
    const float* Abase = g_attn + (size_t)(m0 + a_row) * DIMC;

    GEMM_MAINLOOP(Abase)

#pragma unroll
    for (int i = 0; i < 2; i++) {
#pragma unroll
        for (int j = 0; j < 8; j++) {
            int r0 = m0 + wm * 32 + i * 16 + g;
            int c  = n0 + wn * 64 + j * 8 + t * 2;
            float b0 = bias[c], b1 = bias[c + 1];
            out[(size_t)r0 * DIMC + c]           = acc[i][j][0] + b0;
            out[(size_t)r0 * DIMC + c + 1]       = acc[i][j][1] + b1;
            out[(size_t)(r0 + 8) * DIMC + c]     = acc[i][j][2] + b0;
            out[(size_t)(r0 + 8) * DIMC + c + 1] = acc[i][j][3] + b1;
        }
    }
}

// =======================================================================
// Tensor-core 64-wide MLP machinery — single tf32 (error budget carried
// by the big GEMMs; LN renormalizes each stage). Weights pre-cvt to tf32
// bits in smem; activations cvt at fragment load. 2 CTAs/SM.
// =======================================================================
#define XS_STRIDE 68
#define WS_STRIDE 72
#define MLP_SMEM_FLOATS (256 * XS_STRIDE + 64 * WS_STRIDE + 4 * 64)
#define MLP_SMEM_BYTES  (MLP_SMEM_FLOATS * 4)

__device__ __forceinline__ void load_weights_tf32(
    uint32_t* Ws, const float* __restrict__ src, int tid)
{
    for (int idx = tid; idx < 4096; idx += 256)
        Ws[(idx >> 6) * WS_STRIDE + (idx & 63)] = f2tf32(src[idx]);
}

__device__ __forceinline__ void mma_block64(
    float acc[2][8][4], const float* Xw, const uint32_t* Ws, int g, int t)
{
#pragma unroll
    for (int ks8 = 0; ks8 < 8; ks8++) {
        int ks = ks8 * 8;
        uint32_t af[2][4];
#pragma unroll
        for (int i = 0; i < 2; i++) {
            const float* xr = Xw + (i * 16 + g) * XS_STRIDE + ks;
            af[i][0] = f2tf32(xr[t]);
            af[i][1] = f2tf32(xr[8 * XS_STRIDE + t]);
            af[i][2] = f2tf32(xr[t + 4]);
            af[i][3] = f2tf32(xr[8 * XS_STRIDE + t + 4]);
        }
#pragma unroll
        for (int j = 0; j < 8; j++) {
            int cb = j * 8 + g;
            uint32_t b0 = Ws[(ks + t    ) * WS_STRIDE + cb];
            uint32_t b1 = Ws[(ks + t + 4) * WS_STRIDE + cb];
#pragma unroll
            for (int i = 0; i < 2; i++)
                mma_tf32(acc[i][j], af[i][0], af[i][1], af[i][2], af[i][3], b0, b1);
        }
    }
}

// bias + LN + gelu entirely in registers (quad shuffles for row stats)
__device__ __forceinline__ void ln_gelu_regs(
    float acc[2][8][4], const float* Pb, const float* Pg, const float* Pe, int t)
{
#pragma unroll
    for (int i = 0; i < 2; i++) {
        float s1A = 0, s2A = 0, s1B = 0, s2B = 0;
#pragma unroll
        for (int j = 0; j < 8; j++) {
#pragma unroll
            for (int q = 0; q < 4; q++) {
                int col = j * 8 + t * 2 + (q & 1);
                float v = acc[i][j][q] + Pb[col];
                acc[i][j][q] = v;
                if (q < 2) { s1A += v; s2A += v * v; }
                else       { s1B += v; s2B += v * v; }
            }
        }
        s1A += __shfl_xor_sync(~0u, s1A, 1); s2A += __shfl_xor_sync(~0u, s2A, 1);
        s1B += __shfl_xor_sync(~0u, s1B, 1); s2B += __shfl_xor_sync(~0u, s2B, 1);
        s1A += __shfl_xor_sync(~0u, s1A, 2); s2A += __shfl_xor_sync(~0u, s2A, 2);
        s1B += __shfl_xor_sync(~0u, s1B, 2); s2B += __shfl_xor_sync(~0u, s2B, 2);
        float muA = s1A * (1.0f / 64.0f);
        float muB = s1B * (1.0f / 64.0f);
        float rA = rsqrtf(s2A * (1.0f / 64.0f) - muA * muA + 1e-5f);
        float rB = rsqrtf(s2B * (1.0f / 64.0f) - muB * muB + 1e-5f);
#pragma unroll
        for (int j = 0; j < 8; j++) {
#pragma unroll
            for (int q = 0; q < 4; q++) {
                int col = j * 8 + t * 2 + (q & 1);
                float mu = (q < 2) ? muA : muB;
                float rv = (q < 2) ? rA : rB;
                acc[i][j][q] = gelu_f((acc[i][j][q] - mu) * rv * Pg[col] + Pe[col]);
            }
        }
    }
}

// ---------------- pool stage (tensor core): pair-mean + MLP(LN+gelu) --------
__global__ __launch_bounds__(256, 2) void pool_mlp_tc(
    int stage,
    const float* __restrict__ pW, const float* __restrict__ pb,
    const float* __restrict__ pg, const float* __restrict__ pbe)
{
    extern __shared__ float sm[];
    float*    Xs = sm;
    uint32_t* Ws = (uint32_t*)(sm + 256 * XS_STRIDE);
    float*    Pb = (float*)(Ws + 64 * WS_STRIDE);
    float*    Pg = Pb + 64;
    float*    Pe = Pg + 64;

    const float* in; float* out; int s_in, s_out;
    if (stage == 0)      { in = g_k;   out = g_kcA; s_in = 4096; s_out = 2048; }
    else if (stage == 1) { in = g_kcA; out = g_kcB; s_in = 2048; s_out = 1024; }
    else                 { in = g_kcB; out = g_kcA; s_in = 1024; s_out = 512;  }

    int tid = threadIdx.x, warp = tid >> 5, lane = tid & 31;
    int g = lane >> 2, t = lane & 3;

    // pooled activation load: X row = mean of input rows 2n, 2n+1
    for (int idx = tid; idx < 256 * 16; idx += 256) {
        int r = idx >> 4, c4 = (idx & 15) << 2;
        int rg = blockIdx.x * 256 + r;
        int bh = rg / s_out, n = rg - bh * s_out;
        const float* src = in + ((size_t)bh * s_in + 2 * n) * 64 + c4;
        float4 a = *(const float4*)src;
        float4 b = *(const float4*)(src + 64);
        float4 v;
        v.x = 0.5f * (a.x + b.x); v.y = 0.5f * (a.y + b.y);
        v.z = 0.5f * (a.z + b.z); v.w = 0.5f * (a.w + b.w);
        *(float4*)&Xs[r * XS_STRIDE + c4] = v;
    }
    load_weights_tf32(Ws, pW + stage * 4096, tid);
    if (tid < 64) {
        Pb[tid] = pb[stage * 64 + tid];
        Pg[tid] = pg[stage * 64 + tid];
        Pe[tid] = pbe[stage * 64 + tid];
    }
    __syncthreads();

    float acc[2][8][4];
#pragma unroll
    for (int i = 0; i < 2; i++)
#pragma unroll
        for (int j = 0; j < 8; j++)
#pragma unroll
            for (int q = 0; q < 4; q++) acc[i][j][q] = 0.0f;

    mma_block64(acc, Xs + warp * 32 * XS_STRIDE, Ws, g, t);
    ln_gelu_regs(acc, Pb, Pg, Pe, t);

    float* ob = out + (size_t)(blockIdx.x * 256 + warp * 32) * 64;
#pragma unroll
    for (int i = 0; i < 2; i++) {
#pragma unroll
        for (int j = 0; j < 8; j++) {
            int col = j * 8 + t * 2;
            float2 v0 = make_float2(acc[i][j][0], acc[i][j][1]);
            float2 v1 = make_float2(acc[i][j][2], acc[i][j][3]);
            *(float2*)(ob + (i * 16 + g    ) * 64 + col) = v0;
            *(float2*)(ob + (i * 16 + g + 8) * 64 + col) = v1;
        }
    }
}

// ---------------- fused attention apply + 3 exp MLP stages (tensor core) ----
__global__ __launch_bounds__(256, 2) void attn_mlp_tc(
    const float* __restrict__ eW, const float* __restrict__ eb,
    const float* __restrict__ eg, const float* __restrict__ ebe)
{
    extern __shared__ float sm[];
    float*    Xs  = sm;
    uint32_t* Ws  = (uint32_t*)(sm + 256 * XS_STRIDE);
    float*    Pb  = (float*)(Ws + 64 * WS_STRIDE);
    float*    Pg  = Pb + 64;
    float*    Pe  = Pg + 64;
    float*    Ksm = Pe + 64;

    int tid = threadIdx.x, warp = tid >> 5, lane = tid & 31;
    int g = lane >> 2, t = lane & 3;
    int bh = blockIdx.x >> 4;
    int n0 = (blockIdx.x & 15) << 8;

    const float* qb = g_q + ((size_t)bh * 4096 + n0) * 64;
    for (int idx = tid; idx < 256 * 16; idx += 256) {
        int r = idx >> 4, c4 = (idx & 15) << 2;
        *(float4*)&Xs[r * XS_STRIDE + c4] = *(const float4*)(qb + r * 64 + c4);
    }
    load_weights_tf32(Ws, g_kv + bh * 4096, tid);
    if (tid < 64) Ksm[tid] = g_ksum[bh * 64 + tid];
    __syncthreads();

    const float* Xw  = Xs + warp * 32 * XS_STRIDE;
    float*       Xwm = Xs + warp * 32 * XS_STRIDE;

    float acc[2][8][4];
#pragma unroll
    for (int i = 0; i < 2; i++)
#pragma unroll
        for (int j = 0; j < 8; j++)
#pragma unroll
            for (int q = 0; q < 4; q++) acc[i][j][q] = 0.0f;

    // stage 0: y = q @ kv
    mma_block64(acc, Xw, Ws, g, t);

    // per-row inv = 1/(q . ksum + 1e-6)   (4 rows per lane)
    float inv2[2][2];
#pragma unroll
    for (int i = 0; i < 2; i++) {
#pragma unroll
        for (int hlf = 0; hlf < 2; hlf++) {
            const float* xr = Xw + (i * 16 + g + hlf * 8) * XS_STRIDE;
            float dp = 0.0f;
#pragma unroll
            for (int e = 0; e < 16; e++) dp += xr[t + e * 4] * Ksm[t + e * 4];
            dp += __shfl_xor_sync(~0u, dp, 1);
            dp += __shfl_xor_sync(~0u, dp, 2);
            inv2[i][hlf] = 1.0f / (dp + 1e-6f);
        }
    }
    // scale and write back to warp-private rows
#pragma unroll
    for (int i = 0; i < 2; i++) {
#pragma unroll
        for (int j = 0; j < 8; j++) {
            int col = j * 8 + t * 2;
            float2 v0 = make_float2(acc[i][j][0] * inv2[i][0], acc[i][j][1] * inv2[i][0]);
            float2 v1 = make_float2(acc[i][j][2] * inv2[i][1], acc[i][j][3] * inv2[i][1]);
            *(float2*)&Xwm[(i * 16 + g    ) * XS_STRIDE + col] = v0;
            *(float2*)&Xwm[(i * 16 + g + 8) * XS_STRIDE + col] = v1;
        }
    }

    // exp MLP stages s = 2,1,0
    int b = bh / Hh, h = bh - b * Hh;
    float* obase = g_attn + ((size_t)b * 4096 + n0 + warp * 32) * DIMC + h * 64;

    for (int s = 2; s >= 0; s--) {
        __syncthreads();   // all warps done reading W from previous stage
        load_weights_tf32(Ws, eW + s * 4096, tid);
        if (tid < 64) {
            Pb[tid] = eb[s * 64 + tid];
            Pg[tid] = eg[s * 64 + tid];
            Pe[tid] = ebe[s * 64 + tid];
        }
        __syncthreads();

#pragma unroll
        for (int i = 0; i < 2; i++)
#pragma unroll
            for (int j = 0; j < 8; j++)
#pragma unroll
                for (int q = 0; q < 4; q++) acc[i][j][q] = 0.0f;

        mma_block64(acc, Xw, Ws, g, t);
        ln_gelu_regs(acc, Pb, Pg, Pe, t);

        if (s > 0) {
#pragma unroll
            for (int i = 0; i < 2; i++) {
#pragma unroll
                for (int j = 0; j < 8; j++) {
                    int col = j * 8 + t * 2;
                    *(float2*)&Xwm[(i * 16 + g    ) * XS_STRIDE + col] =
                        make_float2(acc[i][j][0], acc[i][j][1]);
                    *(float2*)&Xwm[(i * 16 + g + 8) * XS_STRIDE + col] =
                        make_float2(acc[i][j][2], acc[i][j][3]);
                }
            }
        } else {
#pragma unroll
            for (int i = 0; i < 2; i++) {
#pragma unroll
                for (int j = 0; j < 8; j++) {
                    int col = j * 8 + t * 2;
                    *(float2*)(obase + (size_t)(i * 16 + g    ) * DIMC + col) =
                        make_float2(acc[i][j][0], acc[i][j][1]);
                    *(float2*)(obase + (size_t)(i * 16 + g + 8) * DIMC + col) =
                        make_float2(acc[i][j][2], acc[i][j][3]);
                }
            }
        }
    }
}

// ---------------- vc pooling: mean over 8 consecutive tokens ----------------
__global__ void vpool_kernel()
{
    int idx = blockIdx.x * 256 + threadIdx.x;
    if (idx >= BH * 512 * Dh) return;
    int d   = idx & 63;
    int rest = idx >> 6;
    int n   = rest & 511;
    int bh  = rest >> 9;
    const float* src = g_v + (bh * 4096 + n * 8) * 64 + d;
    float s = 0.0f;
#pragma unroll
    for (int j = 0; j < 8; j++) s += src[j * 64];
    g_vc[idx] = s * 0.125f;
}

// ---------------- kv = (kc/sqrt(512))^T vc, plus k_sum, per (b,h) -----------
__global__ __launch_bounds__(256) void kv_kernel()
{
    int bh = blockIdx.x;
    __shared__ float ks[64][65];
    __shared__ float vs[64][65];
    int tid = threadIdx.x;
    int td = tid & 15, te = tid >> 4;
    float acc[4][4];
#pragma unroll
    for (int i = 0; i < 4; i++)
#pragma unroll
        for (int j = 0; j < 4; j++) acc[i][j] = 0.0f;
    float colsum = 0.0f;
    const float scale = rsqrtf(512.0f);

    for (int nt = 0; nt < 512; nt += 64) {
        for (int i = tid; i < 4096; i += 256) {
            int rr = i >> 6, cc = i & 63;
            ks[rr][cc] = g_kcA[(bh * 512 + nt + rr) * 64 + cc] * scale;
            vs[rr][cc] = g_vc [(bh * 512 + nt + rr) * 64 + cc];
        }
        __syncthreads();
        if (tid < 64) {
            for (int rr = 0; rr < 64; rr++) colsum += ks[rr][tid];
        }
#pragma unroll 4
        for (int nn = 0; nn < 64; nn++) {
            float a[4], bb[4];
#pragma unroll
            for (int i = 0; i < 4; i++) a[i]  = ks[nn][td * 4 + i];
#pragma unroll
            for (int j = 0; j < 4; j++) bb[j] = vs[nn][te * 4 + j];
#pragma unroll
            for (int i = 0; i < 4; i++)
#pragma unroll
                for (int j = 0; j < 4; j++)
                    acc[i][j] = fmaf(a[i], bb[j], acc[i][j]);
        }
        __syncthreads();
    }
#pragma unroll
    for (int i = 0; i < 4; i++)
#pragma unroll
        for (int j = 0; j < 4; j++)
            g_kv[(bh * 64 + td * 4 + i) * 64 + te * 4 + j] = acc[i][j];
    if (tid < 64) g_ksum[bh * 64 + tid] = colsum;
}

// ---------------- launch --------------------------------------------------
extern "C" void kernel_launch(void* const* d_in, const int* in_sizes, int n_in,
                              void* d_out, int out_size)
{
    const float* x   = (const float*)d_in[0];
    const float* Wq  = (const float*)d_in[1];
    const float* Wk  = (const float*)d_in[2];
    const float* Wv  = (const float*)d_in[3];
    const float* pW  = (const float*)d_in[4];
    const float* pb  = (const float*)d_in[5];
    const float* pg  = (const float*)d_in[6];
    const float* pbe = (const float*)d_in[7];
    const float* eW  = (const float*)d_in[8];
    const float* eb  = (const float*)d_in[9];
    const float* eg  = (const float*)d_in[10];
    const float* ebe = (const float*)d_in[11];
    const float* Wo  = (const float*)d_in[12];
    const float* bo  = (const float*)d_in[13];
    float* out = (float*)d_out;

    cudaFuncSetAttribute(qkv_gemm,
        cudaFuncAttributeMaxDynamicSharedMemorySize, GEMM_SMEM_BYTES);
    cudaFuncSetAttribute(out_gemm,
        cudaFuncAttributeMaxDynamicSharedMemorySize, GEMM_SMEM_BYTES);
    cudaFuncSetAttribute(pool_mlp_tc,
        cudaFuncAttributeMaxDynamicSharedMemorySize, MLP_SMEM_BYTES);
    cudaFuncSetAttribute(attn_mlp_tc,
        cudaFuncAttributeMaxDynamicSharedMemorySize, MLP_SMEM_BYTES);

    qkv_gemm<<<dim3(MR / 128, 18), 256, GEMM_SMEM_BYTES>>>(x, Wq, Wk, Wv);
    vpool_kernel<<<(BH * 512 * Dh + 255) / 256, 256>>>();
    pool_mlp_tc<<<BH * 2048 / 256, 256, MLP_SMEM_BYTES>>>(0, pW, pb, pg, pbe);
    pool_mlp_tc<<<BH * 1024 / 256, 256, MLP_SMEM_BYTES>>>(1, pW, pb, pg, pbe);
    pool_mlp_tc<<<BH * 512 / 256, 256, MLP_SMEM_BYTES>>>(2, pW, pb, pg, pbe);
    kv_kernel<<<BH, 256>>>();
    attn_mlp_tc<<<BH * 16, 256, MLP_SMEM_BYTES>>>(eW, eb, eg, ebe);
    out_gemm<<<dim3(MR / 128, 6), 256, GEMM_SMEM_BYTES>>>(Wo, bo, out);
}